// round 2
// baseline (speedup 1.0000x reference)
#include <cuda_runtime.h>
#include <cuda_bf16.h>
#include <cstdint>
#include <cmath>

#define HIDDEN 3072
#define NHEADS 24
#define NKV 8
#define HD 128
#define ROTD 96
#define OPSZ 5120
#define RLORA 256
#define BB 2
#define SS 2048
#define MTOT (BB*SS)
#define ATT_SCALE 0.08838834764831845f
#define LORA_SC 2.0f

typedef unsigned int u32;

// ---------------- static scratch heap ----------------
constexpr size_t SZ_X    = (size_t)MTOT*HIDDEN;
constexpr size_t SZ_WQKV = (size_t)OPSZ*HIDDEN;
constexpr size_t SZ_AQ   = (size_t)RLORA*HIDDEN;
constexpr size_t SZ_BQ   = (size_t)OPSZ*RLORA;
constexpr size_t SZ_WO   = (size_t)HIDDEN*HIDDEN;
constexpr size_t SZ_BO   = (size_t)HIDDEN*RLORA;
constexpr size_t SZ_QKV  = (size_t)MTOT*OPSZ;
constexpr size_t SZ_T    = (size_t)MTOT*RLORA;
constexpr size_t SZ_Q    = (size_t)BB*NHEADS*SS*HD;
constexpr size_t SZ_KV   = (size_t)BB*NKV*SS*HD;

constexpr size_t al256(size_t x){ return (x+255)&~(size_t)255; }

constexpr size_t O_XHI = 0;
constexpr size_t O_XLO = O_XHI + al256(SZ_X*2);
constexpr size_t O_WQH = O_XLO + al256(SZ_X*2);
constexpr size_t O_WQL = O_WQH + al256(SZ_WQKV*2);
constexpr size_t O_AQH = O_WQL + al256(SZ_WQKV*2);
constexpr size_t O_AQL = O_AQH + al256(SZ_AQ*2);
constexpr size_t O_BQH = O_AQL + al256(SZ_AQ*2);
constexpr size_t O_BQL = O_BQH + al256(SZ_BQ*2);
constexpr size_t O_WOH = O_BQL + al256(SZ_BQ*2);
constexpr size_t O_WOL = O_WOH + al256(SZ_WO*2);
constexpr size_t O_AOH = O_WOL + al256(SZ_WO*2);
constexpr size_t O_AOL = O_AOH + al256(SZ_AQ*2);
constexpr size_t O_BOH = O_AOL + al256(SZ_AQ*2);
constexpr size_t O_BOL = O_BOH + al256(SZ_BO*2);
constexpr size_t O_T1H = O_BOL + al256(SZ_BO*2);
constexpr size_t O_T1L = O_T1H + al256(SZ_T*2);
constexpr size_t O_T2H = O_T1L + al256(SZ_T*2);
constexpr size_t O_T2L = O_T2H + al256(SZ_T*2);
constexpr size_t O_QH  = O_T2L + al256(SZ_T*2);
constexpr size_t O_QL  = O_QH  + al256(SZ_Q*2);
constexpr size_t O_KH  = O_QL  + al256(SZ_Q*2);
constexpr size_t O_KL  = O_KH  + al256(SZ_KV*2);
constexpr size_t O_VH  = O_KL  + al256(SZ_KV*2);
constexpr size_t O_VL  = O_VH  + al256(SZ_KV*2);
constexpr size_t O_ATH = O_VL  + al256(SZ_KV*2);
constexpr size_t O_ATL = O_ATH + al256(SZ_X*2);
constexpr size_t O_QKV = O_ATL + al256(SZ_X*2);
constexpr size_t O_T1  = O_QKV + al256(SZ_QKV*4);
constexpr size_t O_T2  = O_T1  + al256(SZ_T*4);
constexpr size_t O_ATT = O_T2  + al256(SZ_T*4);
constexpr size_t HEAP_BYTES = O_ATT + al256(SZ_X*4);

__device__ __align__(256) unsigned char g_heap[HEAP_BYTES];

// ---------------- helpers ----------------
__device__ __forceinline__ void mma16816(float* c, const u32* a, const u32* b) {
    asm volatile("mma.sync.aligned.m16n8k16.row.col.f32.bf16.bf16.f32 "
        "{%0,%1,%2,%3}, {%4,%5,%6,%7}, {%8,%9}, {%0,%1,%2,%3};\n"
        : "+f"(c[0]), "+f"(c[1]), "+f"(c[2]), "+f"(c[3])
        : "r"(a[0]), "r"(a[1]), "r"(a[2]), "r"(a[3]), "r"(b[0]), "r"(b[1]));
}
__device__ __forceinline__ void cp_async16(void* smem, const void* g) {
    u32 sa = (u32)__cvta_generic_to_shared(smem);
    asm volatile("cp.async.cg.shared.global [%0], [%1], 16;\n" :: "r"(sa), "l"(g));
}
#define CP_COMMIT() asm volatile("cp.async.commit_group;\n")
#define CP_WAIT1()  asm volatile("cp.async.wait_group 1;\n")

__device__ __forceinline__ void split_pack(float x, float y, u32& hi, u32& lo) {
    __nv_bfloat16 hx = __float2bfloat16(x);
    __nv_bfloat16 hy = __float2bfloat16(y);
    __nv_bfloat16 lx = __float2bfloat16(x - __bfloat162float(hx));
    __nv_bfloat16 ly = __float2bfloat16(y - __bfloat162float(hy));
    hi = ((u32)__bfloat16_as_ushort(hy) << 16) | (u32)__bfloat16_as_ushort(hx);
    lo = ((u32)__bfloat16_as_ushort(ly) << 16) | (u32)__bfloat16_as_ushort(lx);
}

// ---------------- fp32 -> bf16 hi/lo split ----------------
__global__ void split_fp32(const float* __restrict__ in,
                           __nv_bfloat16* __restrict__ hi,
                           __nv_bfloat16* __restrict__ lo, size_t n4) {
    size_t i = (size_t)blockIdx.x * blockDim.x + threadIdx.x;
    if (i >= n4) return;
    float4 v = ((const float4*)in)[i];
    u32 h0, l0, h1, l1;
    split_pack(v.x, v.y, h0, l0);
    split_pack(v.z, v.w, h1, l1);
    ((uint2*)hi)[i] = make_uint2(h0, h1);
    ((uint2*)lo)[i] = make_uint2(l0, l1);
}

// ---------------- GEMM: C[M,N] (+)= alpha * A[M,K] @ B[N,K]^T, split-bf16 3-pass ----------------
#define GBK 32
#define GPK 40
#define GARR (128*GPK)
#define GSTAGE (4*GARR)

__global__ void __launch_bounds__(256) gemm_split(
    const __nv_bfloat16* __restrict__ Ahi, const __nv_bfloat16* __restrict__ Alo,
    const __nv_bfloat16* __restrict__ Bhi, const __nv_bfloat16* __restrict__ Blo,
    float* __restrict__ C, int M, int N, int K, float alpha, int beta)
{
    extern __shared__ __nv_bfloat16 sm[];
    int tid = threadIdx.x;
    int bm = blockIdx.y * 128, bn = blockIdx.x * 128;
    int warp = tid >> 5, lane = tid & 31;
    int wm = warp >> 1, wn = warp & 1;
    int g = lane >> 2, tg = lane & 3;

    auto load_stage = [&](int stage, int k0) {
        __nv_bfloat16* base = sm + stage * GSTAGE;
        #pragma unroll
        for (int i = 0; i < 8; ++i) {
            int task = tid + i * 256;
            int arr = task >> 9;
            int rem = task & 511;
            int row = rem >> 2;
            int ch  = rem & 3;
            const __nv_bfloat16* gsrc;
            if (arr == 0)      gsrc = Ahi + (size_t)(bm + row) * K + k0 + ch * 8;
            else if (arr == 1) gsrc = Alo + (size_t)(bm + row) * K + k0 + ch * 8;
            else if (arr == 2) gsrc = Bhi + (size_t)(bn + row) * K + k0 + ch * 8;
            else               gsrc = Blo + (size_t)(bn + row) * K + k0 + ch * 8;
            cp_async16(base + arr * GARR + row * GPK + ch * 8, gsrc);
        }
    };

    float acc[2][8][4];
    #pragma unroll
    for (int a = 0; a < 2; ++a)
        #pragma unroll
        for (int b = 0; b < 8; ++b)
            #pragma unroll
            for (int c = 0; c < 4; ++c) acc[a][b][c] = 0.f;

    int nkt = K / GBK;
    load_stage(0, 0);
    CP_COMMIT();
    for (int kt = 0; kt < nkt; ++kt) {
        if (kt + 1 < nkt) load_stage((kt + 1) & 1, (kt + 1) * GBK);
        CP_COMMIT();
        CP_WAIT1();
        __syncthreads();
        const __nv_bfloat16* base = sm + (kt & 1) * GSTAGE;
        const __nv_bfloat16* sAh = base;
        const __nv_bfloat16* sAl = base + GARR;
        const __nv_bfloat16* sBh = base + 2 * GARR;
        const __nv_bfloat16* sBl = base + 3 * GARR;
        #pragma unroll
        for (int ks = 0; ks < 2; ++ks) {
            int k0 = ks * 16;
            u32 ah[2][4], al[2][4];
            #pragma unroll
            for (int mt = 0; mt < 2; ++mt) {
                int r0 = wm * 32 + mt * 16;
                const __nv_bfloat16* ph = sAh + (r0 + g) * GPK + k0 + 2 * tg;
                ah[mt][0] = *(const u32*)ph;
                ah[mt][1] = *(const u32*)(ph + 8 * GPK);
                ah[mt][2] = *(const u32*)(ph + 8);
                ah[mt][3] = *(const u32*)(ph + 8 * GPK + 8);
                const __nv_bfloat16* pl = sAl + (r0 + g) * GPK + k0 + 2 * tg;
                al[mt][0] = *(const u32*)pl;
                al[mt][1] = *(const u32*)(pl + 8 * GPK);
                al[mt][2] = *(const u32*)(pl + 8);
                al[mt][3] = *(const u32*)(pl + 8 * GPK + 8);
            }
            #pragma unroll
            for (int nt = 0; nt < 8; ++nt) {
                int c0 = wn * 64 + nt * 8;
                const __nv_bfloat16* pbh = sBh + (c0 + g) * GPK + k0 + 2 * tg;
                const __nv_bfloat16* pbl = sBl + (c0 + g) * GPK + k0 + 2 * tg;
                u32 bh[2] = { *(const u32*)pbh, *(const u32*)(pbh + 8) };
                u32 bl[2] = { *(const u32*)pbl, *(const u32*)(pbl + 8) };
                #pragma unroll
                for (int mt = 0; mt < 2; ++mt) {
                    mma16816(acc[mt][nt], ah[mt], bh);
                    mma16816(acc[mt][nt], ah[mt], bl);
                    mma16816(acc[mt][nt], al[mt], bh);
                }
            }
        }
        __syncthreads();
    }

    #pragma unroll
    for (int mt = 0; mt < 2; ++mt)
        #pragma unroll
        for (int nt = 0; nt < 8; ++nt) {
            int row = bm + wm * 32 + mt * 16 + g;
            int col = bn + wn * 64 + nt * 8 + 2 * tg;
            float* p0 = C + (size_t)row * N + col;
            float* p1 = C + (size_t)(row + 8) * N + col;
            if (beta) {
                p0[0] += alpha * acc[mt][nt][0];
                p0[1] += alpha * acc[mt][nt][1];
                p1[0] += alpha * acc[mt][nt][2];
                p1[1] += alpha * acc[mt][nt][3];
            } else {
                p0[0] = alpha * acc[mt][nt][0];
                p0[1] = alpha * acc[mt][nt][1];
                p1[0] = alpha * acc[mt][nt][2];
                p1[1] = alpha * acc[mt][nt][3];
            }
        }
}

// ---------------- RoPE + split + scatter to [b,h,s,d] ----------------
__global__ void __launch_bounds__(256) rope_split(
    const float* __restrict__ qkv, const int* __restrict__ pos_ids,
    __nv_bfloat16* __restrict__ Qh, __nv_bfloat16* __restrict__ Ql,
    __nv_bfloat16* __restrict__ Kh, __nv_bfloat16* __restrict__ Kl,
    __nv_bfloat16* __restrict__ Vh, __nv_bfloat16* __restrict__ Vl)
{
    int bs = blockIdx.x;
    int b = bs / SS, s = bs % SS;
    __shared__ float cosv[ROTD], sinv[ROTD];
    int tid = threadIdx.x;
    if (tid < 48) {
        float invf = (float)pow(10000.0, -(double)tid / 48.0);  // match ref fp32 inv_freq
        float ang = (float)pos_ids[bs] * invf;                  // match ref fp32 multiply
        float c = (float)cos((double)ang), sn = (float)sin((double)ang);
        cosv[tid] = c; cosv[tid + 48] = c;
        sinv[tid] = sn; sinv[tid + 48] = sn;
    }
    __syncthreads();
    const float* src = qkv + (size_t)bs * OPSZ;
    for (int e = tid; e < OPSZ; e += 256) {
        int d = e & 127;
        int hh = e >> 7;
        float v = src[e];
        bool isq = hh < NHEADS;
        bool isk = (hh >= NHEADS) && (hh < NHEADS + NKV);
        float outv = v;
        if ((isq || isk) && d < ROTD) {
            if (d < 48) outv = v * cosv[d] - src[e + 48] * sinv[d];
            else        outv = v * cosv[d] + src[e - 48] * sinv[d];
        }
        __nv_bfloat16 hi = __float2bfloat16(outv);
        __nv_bfloat16 lo = __float2bfloat16(outv - __bfloat162float(hi));
        if (isq) {
            size_t dst = ((size_t)(b * NHEADS + hh) * SS + s) * HD + d;
            Qh[dst] = hi; Ql[dst] = lo;
        } else if (isk) {
            size_t dst = ((size_t)(b * NKV + (hh - NHEADS)) * SS + s) * HD + d;
            Kh[dst] = hi; Kl[dst] = lo;
        } else {
            size_t dst = ((size_t)(b * NKV + (hh - NHEADS - NKV)) * SS + s) * HD + d;
            Vh[dst] = hi; Vl[dst] = lo;
        }
    }
}

// ---------------- causal flash attention (GQA), split-bf16 ----------------
#define FQP 136
#define FVP 72

__global__ void __launch_bounds__(128) flash_attn(
    const __nv_bfloat16* __restrict__ Qh, const __nv_bfloat16* __restrict__ Ql,
    const __nv_bfloat16* __restrict__ Kh, const __nv_bfloat16* __restrict__ Kl,
    const __nv_bfloat16* __restrict__ Vh, const __nv_bfloat16* __restrict__ Vl,
    float* __restrict__ attn)
{
    extern __shared__ __nv_bfloat16 fsm[];
    __nv_bfloat16* sQh = fsm;
    __nv_bfloat16* sQl = fsm + 64 * FQP;
    __nv_bfloat16* sKh = fsm + 2 * 64 * FQP;
    __nv_bfloat16* sKl = fsm + 3 * 64 * FQP;
    __nv_bfloat16* sVh = fsm + 4 * 64 * FQP;
    __nv_bfloat16* sVl = fsm + 4 * 64 * FQP + 128 * FVP;

    int qt = blockIdx.x, h = blockIdx.y, b = blockIdx.z;
    int kvh = h / (NHEADS / NKV);
    int tid = threadIdx.x, warp = tid >> 5, lane = tid & 31;
    int g = lane >> 2, tg = lane & 3;

    size_t qbase = ((size_t)(b * NHEADS + h) * SS + (size_t)qt * 64) * HD;
    #pragma unroll
    for (int i = 0; i < 8; ++i) {
        int task = tid + i * 128;
        int row = task >> 4, ch = task & 15;
        *(uint4*)(sQh + row * FQP + ch * 8) = *(const uint4*)(Qh + qbase + row * HD + ch * 8);
        *(uint4*)(sQl + row * FQP + ch * 8) = *(const uint4*)(Ql + qbase + row * HD + ch * 8);
    }

    float m0 = -1e30f, m1 = -1e30f, l0 = 0.f, l1 = 0.f;
    float oacc[16][4];
    #pragma unroll
    for (int i = 0; i < 16; ++i)
        #pragma unroll
        for (int r = 0; r < 4; ++r) oacc[i][r] = 0.f;

    __syncthreads();

    for (int kt = 0; kt <= qt; ++kt) {
        size_t kbase = ((size_t)(b * NKV + kvh) * SS + (size_t)kt * 64) * HD;
        #pragma unroll
        for (int i = 0; i < 8; ++i) {
            int task = tid + i * 128;
            int row = task >> 4, ch = task & 15;
            *(uint4*)(sKh + row * FQP + ch * 8) = *(const uint4*)(Kh + kbase + row * HD + ch * 8);
            *(uint4*)(sKl + row * FQP + ch * 8) = *(const uint4*)(Kl + kbase + row * HD + ch * 8);
            uint4 vh4 = *(const uint4*)(Vh + kbase + row * HD + ch * 8);
            uint4 vl4 = *(const uint4*)(Vl + kbase + row * HD + ch * 8);
            const __nv_bfloat16* eh = (const __nv_bfloat16*)&vh4;
            const __nv_bfloat16* el = (const __nv_bfloat16*)&vl4;
            #pragma unroll
            for (int j = 0; j < 8; ++j) {
                sVh[(ch * 8 + j) * FVP + row] = eh[j];
                sVl[(ch * 8 + j) * FVP + row] = el[j];
            }
        }
        __syncthreads();

        float sacc[8][4];
        #pragma unroll
        for (int nt = 0; nt < 8; ++nt)
            #pragma unroll
            for (int r = 0; r < 4; ++r) sacc[nt][r] = 0.f;

        #pragma unroll
        for (int kc = 0; kc < 8; ++kc) {
            u32 ah[4], al[4];
            const __nv_bfloat16* ph = sQh + (warp * 16 + g) * FQP + kc * 16 + 2 * tg;
            const __nv_bfloat16* pl = sQl + (warp * 16 + g) * FQP + kc * 16 + 2 * tg;
            ah[0] = *(const u32*)ph;       ah[1] = *(const u32*)(ph + 8 * FQP);
            ah[2] = *(const u32*)(ph + 8); ah[3] = *(const u32*)(ph + 8 * FQP + 8);
            al[0] = *(const u32*)pl;       al[1] = *(const u32*)(pl + 8 * FQP);
            al[2] = *(const u32*)(pl + 8); al[3] = *(const u32*)(pl + 8 * FQP + 8);
            #pragma unroll
            for (int nt = 0; nt < 8; ++nt) {
                const __nv_bfloat16* pbh = sKh + (nt * 8 + g) * FQP + kc * 16 + 2 * tg;
                const __nv_bfloat16* pbl = sKl + (nt * 8 + g) * FQP + kc * 16 + 2 * tg;
                u32 bh[2] = { *(const u32*)pbh, *(const u32*)(pbh + 8) };
                u32 bl[2] = { *(const u32*)pbl, *(const u32*)(pbl + 8) };
                mma16816(sacc[nt], ah, bh);
                mma16816(sacc[nt], ah, bl);
                mma16816(sacc[nt], al, bh);
            }
        }

        bool diag = (kt == qt);
        int row0 = qt * 64 + warp * 16 + g;
        #pragma unroll
        for (int nt = 0; nt < 8; ++nt)
            #pragma unroll
            for (int r = 0; r < 4; ++r) {
                float v = sacc[nt][r] * ATT_SCALE;
                if (diag) {
                    int col = kt * 64 + nt * 8 + 2 * tg + (r & 1);
                    int row = row0 + ((r >= 2) ? 8 : 0);
                    if (col > row) v = -1e30f;
                }
                sacc[nt][r] = v;
            }

        float rm0 = -1e30f, rm1 = -1e30f;
        #pragma unroll
        for (int nt = 0; nt < 8; ++nt) {
            rm0 = fmaxf(rm0, fmaxf(sacc[nt][0], sacc[nt][1]));
            rm1 = fmaxf(rm1, fmaxf(sacc[nt][2], sacc[nt][3]));
        }
        rm0 = fmaxf(rm0, __shfl_xor_sync(0xffffffffu, rm0, 1));
        rm0 = fmaxf(rm0, __shfl_xor_sync(0xffffffffu, rm0, 2));
        rm1 = fmaxf(rm1, __shfl_xor_sync(0xffffffffu, rm1, 1));
        rm1 = fmaxf(rm1, __shfl_xor_sync(0xffffffffu, rm1, 2));
        float nm0 = fmaxf(m0, rm0), nm1 = fmaxf(m1, rm1);
        float alpha0 = __expf(m0 - nm0), alpha1 = __expf(m1 - nm1);
        m0 = nm0; m1 = nm1;
        float rs0 = 0.f, rs1 = 0.f;
        #pragma unroll
        for (int nt = 0; nt < 8; ++nt) {
            sacc[nt][0] = __expf(sacc[nt][0] - m0); rs0 += sacc[nt][0];
            sacc[nt][1] = __expf(sacc[nt][1] - m0); rs0 += sacc[nt][1];
            sacc[nt][2] = __expf(sacc[nt][2] - m1); rs1 += sacc[nt][2];
            sacc[nt][3] = __expf(sacc[nt][3] - m1); rs1 += sacc[nt][3];
        }
        rs0 += __shfl_xor_sync(0xffffffffu, rs0, 1);
        rs0 += __shfl_xor_sync(0xffffffffu, rs0, 2);
        rs1 += __shfl_xor_sync(0xffffffffu, rs1, 1);
        rs1 += __shfl_xor_sync(0xffffffffu, rs1, 2);
        l0 = l0 * alpha0 + rs0;
        l1 = l1 * alpha1 + rs1;
        #pragma unroll
        for (int nt = 0; nt < 16; ++nt) {
            oacc[nt][0] *= alpha0; oacc[nt][1] *= alpha0;
            oacc[nt][2] *= alpha1; oacc[nt][3] *= alpha1;
        }

        #pragma unroll
        for (int kc2 = 0; kc2 < 4; ++kc2) {
            u32 ph4[4], pl4[4];
            split_pack(sacc[2 * kc2][0],     sacc[2 * kc2][1],     ph4[0], pl4[0]);
            split_pack(sacc[2 * kc2][2],     sacc[2 * kc2][3],     ph4[1], pl4[1]);
            split_pack(sacc[2 * kc2 + 1][0], sacc[2 * kc2 + 1][1], ph4[2], pl4[2]);
            split_pack(sacc[2 * kc2 + 1][2], sacc[2 * kc2 + 1][3], ph4[3], pl4[3]);
            #pragma unroll
            for (int nt = 0; nt < 16; ++nt) {
                const __nv_bfloat16* pbh = sVh + (nt * 8 + g) * FVP + kc2 * 16 + 2 * tg;
                const __nv_bfloat16* pbl = sVl + (nt * 8 + g) * FVP + kc2 * 16 + 2 * tg;
                u32 bh[2] = { *(const u32*)pbh, *(const u32*)(pbh + 8) };
                u32 bl[2] = { *(const u32*)pbl, *(const u32*)(pbl + 8) };
                mma16816(oacc[nt], ph4, bh);
                mma16816(oacc[nt], ph4, bl);
                mma16816(oacc[nt], pl4, bh);
            }
        }
        __syncthreads();
    }

    float inv0 = 1.f / l0, inv1 = 1.f / l1;
    int srow = qt * 64 + warp * 16 + g;
    #pragma unroll
    for (int nt = 0; nt < 16; ++nt) {
        int col = nt * 8 + 2 * tg;
        float* o0 = attn + (size_t)(b * SS + srow) * HIDDEN + h * HD + col;
        float* o1 = attn + (size_t)(b * SS + srow + 8) * HIDDEN + h * HD + col;
        o0[0] = oacc[nt][0] * inv0;
        o0[1] = oacc[nt][1] * inv0;
        o1[0] = oacc[nt][2] * inv1;
        o1[1] = oacc[nt][3] * inv1;
    }
}

// ---------------- launch ----------------
static inline void do_split(const float* src, unsigned char* heap, size_t ohi, size_t olo, size_t n) {
    size_t n4 = n / 4;
    split_fp32<<<(unsigned)((n4 + 255) / 256), 256>>>(
        src, (__nv_bfloat16*)(heap + ohi), (__nv_bfloat16*)(heap + olo), n4);
}

extern "C" void kernel_launch(void* const* d_in, const int* in_sizes, int n_in,
                              void* d_out, int out_size) {
    const float* x    = (const float*)d_in[0];
    const float* Wqkv = (const float*)d_in[1];
    const float* Aqkv = (const float*)d_in[2];
    const float* Bqkv = (const float*)d_in[3];
    const float* Wo   = (const float*)d_in[4];
    const float* Ao   = (const float*)d_in[5];
    const float* Bo   = (const float*)d_in[6];
    const int*   pos  = (const int*)d_in[7];
    float* out = (float*)d_out;

    unsigned char* heap = nullptr;
    cudaGetSymbolAddress((void**)&heap, g_heap);

    size_t gemm_smem = 2 * GSTAGE * sizeof(__nv_bfloat16);
    size_t flash_smem = (4 * 64 * FQP + 2 * 128 * FVP) * sizeof(__nv_bfloat16);
    cudaFuncSetAttribute(gemm_split, cudaFuncAttributeMaxDynamicSharedMemorySize, (int)gemm_smem);
    cudaFuncSetAttribute(flash_attn, cudaFuncAttributeMaxDynamicSharedMemorySize, (int)flash_smem);

#define BF(off) ((__nv_bfloat16*)(heap + off))
#define FP(off) ((float*)(heap + off))

    // split inputs
    do_split(x,    heap, O_XHI, O_XLO, SZ_X);
    do_split(Wqkv, heap, O_WQH, O_WQL, SZ_WQKV);
    do_split(Aqkv, heap, O_AQH, O_AQL, SZ_AQ);
    do_split(Bqkv, heap, O_BQH, O_BQL, SZ_BQ);
    do_split(Wo,   heap, O_WOH, O_WOL, SZ_WO);
    do_split(Ao,   heap, O_AOH, O_AOL, SZ_AQ);
    do_split(Bo,   heap, O_BOH, O_BOL, SZ_BO);

    // QKV = x @ Wqkv^T
    gemm_split<<<dim3(OPSZ / 128, MTOT / 128), 256, gemm_smem>>>(
        BF(O_XHI), BF(O_XLO), BF(O_WQH), BF(O_WQL), FP(O_QKV),
        MTOT, OPSZ, HIDDEN, 1.0f, 0);
    // T1 = x @ Aqkv^T
    gemm_split<<<dim3(RLORA / 128, MTOT / 128), 256, gemm_smem>>>(
        BF(O_XHI), BF(O_XLO), BF(O_AQH), BF(O_AQL), FP(O_T1),
        MTOT, RLORA, HIDDEN, 1.0f, 0);
    do_split(FP(O_T1), heap, O_T1H, O_T1L, SZ_T);
    // QKV += LORA_SC * T1 @ Bqkv^T
    gemm_split<<<dim3(OPSZ / 128, MTOT / 128), 256, gemm_smem>>>(
        BF(O_T1H), BF(O_T1L), BF(O_BQH), BF(O_BQL), FP(O_QKV),
        MTOT, OPSZ, RLORA, LORA_SC, 1);

    // RoPE + scatter + split
    rope_split<<<MTOT, 256>>>(FP(O_QKV), pos,
        BF(O_QH), BF(O_QL), BF(O_KH), BF(O_KL), BF(O_VH), BF(O_VL));

    // flash attention
    flash_attn<<<dim3(SS / 64, NHEADS, BB), 128, flash_smem>>>(
        BF(O_QH), BF(O_QL), BF(O_KH), BF(O_KL), BF(O_VH), BF(O_VL), FP(O_ATT));

    // output projection
    do_split(FP(O_ATT), heap, O_ATH, O_ATL, SZ_X);
    gemm_split<<<dim3(HIDDEN / 128, MTOT / 128), 256, gemm_smem>>>(
        BF(O_ATH), BF(O_ATL), BF(O_WOH), BF(O_WOL), out,
        MTOT, HIDDEN, HIDDEN, 1.0f, 0);
    gemm_split<<<dim3(RLORA / 128, MTOT / 128), 256, gemm_smem>>>(
        BF(O_ATH), BF(O_ATL), BF(O_AOH), BF(O_AOL), FP(O_T2),
        MTOT, RLORA, HIDDEN, 1.0f, 0);
    do_split(FP(O_T2), heap, O_T2H, O_T2L, SZ_T);
    gemm_split<<<dim3(HIDDEN / 128, MTOT / 128), 256, gemm_smem>>>(
        BF(O_T2H), BF(O_T2L), BF(O_BOH), BF(O_BOL), out,
        MTOT, HIDDEN, RLORA, LORA_SC, 1);

#undef BF
#undef FP
}

// round 3
// speedup vs baseline: 1.3636x; 1.3636x over previous
#include <cuda_runtime.h>
#include <cuda_bf16.h>
#include <cstdint>
#include <cmath>

#define HIDDEN 3072
#define NHEADS 24
#define NKV 8
#define HD 128
#define ROTD 96
#define OPSZ 5120
#define RLORA 256
#define BB 2
#define SS 2048
#define MTOT (BB*SS)
#define ATT_SCALE 0.08838834764831845f
#define LORA_SC 2.0f

typedef unsigned int u32;

// ---------------- static scratch heap ----------------
constexpr size_t SZ_X    = (size_t)MTOT*HIDDEN;
constexpr size_t SZ_WQKV = (size_t)OPSZ*HIDDEN;
constexpr size_t SZ_AQ   = (size_t)RLORA*HIDDEN;
constexpr size_t SZ_BQ   = (size_t)OPSZ*RLORA;
constexpr size_t SZ_WO   = (size_t)HIDDEN*HIDDEN;
constexpr size_t SZ_BO   = (size_t)HIDDEN*RLORA;
constexpr size_t SZ_QKV  = (size_t)MTOT*OPSZ;
constexpr size_t SZ_T    = (size_t)MTOT*RLORA;
constexpr size_t SZ_Q    = (size_t)BB*NHEADS*SS*HD;
constexpr size_t SZ_KV   = (size_t)BB*NKV*SS*HD;

constexpr size_t al256(size_t x){ return (x+255)&~(size_t)255; }

constexpr size_t O_XHI = 0;
constexpr size_t O_XLO = O_XHI + al256(SZ_X*2);
constexpr size_t O_WQH = O_XLO + al256(SZ_X*2);
constexpr size_t O_WQL = O_WQH + al256(SZ_WQKV*2);
constexpr size_t O_AQH = O_WQL + al256(SZ_WQKV*2);
constexpr size_t O_AQL = O_AQH + al256(SZ_AQ*2);
constexpr size_t O_BQH = O_AQL + al256(SZ_AQ*2);
constexpr size_t O_BQL = O_BQH + al256(SZ_BQ*2);
constexpr size_t O_WOH = O_BQL + al256(SZ_BQ*2);
constexpr size_t O_WOL = O_WOH + al256(SZ_WO*2);
constexpr size_t O_AOH = O_WOL + al256(SZ_WO*2);
constexpr size_t O_AOL = O_AOH + al256(SZ_AQ*2);
constexpr size_t O_BOH = O_AOL + al256(SZ_AQ*2);
constexpr size_t O_BOL = O_BOH + al256(SZ_BO*2);
constexpr size_t O_T1H = O_BOL + al256(SZ_BO*2);
constexpr size_t O_T1L = O_T1H + al256(SZ_T*2);
constexpr size_t O_T2H = O_T1L + al256(SZ_T*2);
constexpr size_t O_T2L = O_T2H + al256(SZ_T*2);
constexpr size_t O_QH  = O_T2L + al256(SZ_T*2);
constexpr size_t O_QL  = O_QH  + al256(SZ_Q*2);
constexpr size_t O_KH  = O_QL  + al256(SZ_Q*2);
constexpr size_t O_KL  = O_KH  + al256(SZ_KV*2);
constexpr size_t O_VH  = O_KL  + al256(SZ_KV*2);
constexpr size_t O_VL  = O_VH  + al256(SZ_KV*2);
constexpr size_t O_ATH = O_VL  + al256(SZ_KV*2);
constexpr size_t O_ATL = O_ATH + al256(SZ_X*2);
constexpr size_t O_QKV = O_ATL + al256(SZ_X*2);
constexpr size_t HEAP_BYTES = O_QKV + al256(SZ_QKV*4);

__device__ __align__(256) unsigned char g_heap[HEAP_BYTES];

// ---------------- helpers ----------------
__device__ __forceinline__ void mma16816(float* c, const u32* a, const u32* b) {
    asm volatile("mma.sync.aligned.m16n8k16.row.col.f32.bf16.bf16.f32 "
        "{%0,%1,%2,%3}, {%4,%5,%6,%7}, {%8,%9}, {%0,%1,%2,%3};\n"
        : "+f"(c[0]), "+f"(c[1]), "+f"(c[2]), "+f"(c[3])
        : "r"(a[0]), "r"(a[1]), "r"(a[2]), "r"(a[3]), "r"(b[0]), "r"(b[1]));
}
__device__ __forceinline__ void cp_async16(void* smem, const void* g) {
    u32 sa = (u32)__cvta_generic_to_shared(smem);
    asm volatile("cp.async.cg.shared.global [%0], [%1], 16;\n" :: "r"(sa), "l"(g));
}
#define CP_COMMIT() asm volatile("cp.async.commit_group;\n")
#define CP_WAIT1()  asm volatile("cp.async.wait_group 1;\n")
#define CP_WAIT0()  asm volatile("cp.async.wait_group 0;\n")

__device__ __forceinline__ void ldsm4(u32& r0, u32& r1, u32& r2, u32& r3, const __nv_bfloat16* p) {
    u32 a = (u32)__cvta_generic_to_shared(p);
    asm volatile("ldmatrix.sync.aligned.m8n8.x4.shared.b16 {%0,%1,%2,%3}, [%4];\n"
        : "=r"(r0), "=r"(r1), "=r"(r2), "=r"(r3) : "r"(a));
}
__device__ __forceinline__ void ldsm4t(u32& r0, u32& r1, u32& r2, u32& r3, const __nv_bfloat16* p) {
    u32 a = (u32)__cvta_generic_to_shared(p);
    asm volatile("ldmatrix.sync.aligned.m8n8.x4.trans.shared.b16 {%0,%1,%2,%3}, [%4];\n"
        : "=r"(r0), "=r"(r1), "=r"(r2), "=r"(r3) : "r"(a));
}

__device__ __forceinline__ void split_pack(float x, float y, u32& hi, u32& lo) {
    __nv_bfloat16 hx = __float2bfloat16(x);
    __nv_bfloat16 hy = __float2bfloat16(y);
    __nv_bfloat16 lx = __float2bfloat16(x - __bfloat162float(hx));
    __nv_bfloat16 ly = __float2bfloat16(y - __bfloat162float(hy));
    hi = ((u32)__bfloat16_as_ushort(hy) << 16) | (u32)__bfloat16_as_ushort(hx);
    lo = ((u32)__bfloat16_as_ushort(ly) << 16) | (u32)__bfloat16_as_ushort(lx);
}

// ---------------- fp32 -> bf16 hi/lo split ----------------
__global__ void split_fp32(const float* __restrict__ in,
                           __nv_bfloat16* __restrict__ hi,
                           __nv_bfloat16* __restrict__ lo, size_t n4) {
    size_t i = (size_t)blockIdx.x * blockDim.x + threadIdx.x;
    if (i >= n4) return;
    float4 v = ((const float4*)in)[i];
    u32 h0, l0, h1, l1;
    split_pack(v.x, v.y, h0, l0);
    split_pack(v.z, v.w, h1, l1);
    ((uint2*)hi)[i] = make_uint2(h0, h1);
    ((uint2*)lo)[i] = make_uint2(l0, l1);
}

// ---------------- GEMM: C[M,N] (+)= alpha * A[M,K] @ B[N,K]^T ----------------
// If OutHi != nullptr: instead writes split bf16 hi/lo of alpha*acc.
#define GBK 32
#define GPK 40
#define GARR (128*GPK)
#define GSTAGE (4*GARR)

__global__ void __launch_bounds__(256, 2) gemm_split(
    const __nv_bfloat16* __restrict__ Ahi, const __nv_bfloat16* __restrict__ Alo,
    const __nv_bfloat16* __restrict__ Bhi, const __nv_bfloat16* __restrict__ Blo,
    float* __restrict__ C,
    __nv_bfloat16* __restrict__ OutHi, __nv_bfloat16* __restrict__ OutLo,
    int M, int N, int K, float alpha, int beta)
{
    extern __shared__ __nv_bfloat16 sm[];
    int tid = threadIdx.x;
    int bm = blockIdx.y * 128, bn = blockIdx.x * 128;
    int warp = tid >> 5, lane = tid & 31;
    int wm = warp >> 1, wn = warp & 1;
    int g = lane >> 2, tg = lane & 3;

    auto load_stage = [&](int stage, int k0) {
        __nv_bfloat16* base = sm + stage * GSTAGE;
        #pragma unroll
        for (int i = 0; i < 8; ++i) {
            int task = tid + i * 256;
            int arr = task >> 9;
            int rem = task & 511;
            int row = rem >> 2;
            int ch  = rem & 3;
            const __nv_bfloat16* gsrc;
            if (arr == 0)      gsrc = Ahi + (size_t)(bm + row) * K + k0 + ch * 8;
            else if (arr == 1) gsrc = Alo + (size_t)(bm + row) * K + k0 + ch * 8;
            else if (arr == 2) gsrc = Bhi + (size_t)(bn + row) * K + k0 + ch * 8;
            else               gsrc = Blo + (size_t)(bn + row) * K + k0 + ch * 8;
            cp_async16(base + arr * GARR + row * GPK + ch * 8, gsrc);
        }
    };

    float acc[2][8][4];
    #pragma unroll
    for (int a = 0; a < 2; ++a)
        #pragma unroll
        for (int b = 0; b < 8; ++b)
            #pragma unroll
            for (int c = 0; c < 4; ++c) acc[a][b][c] = 0.f;

    // ldmatrix per-lane address components
    int a_row = lane & 15;
    int a_col = (lane >> 4) << 3;
    int b_row = (lane & 7) + ((lane >> 4) << 3);
    int b_col = ((lane >> 3) & 1) << 3;

    int nkt = K / GBK;
    load_stage(0, 0);
    CP_COMMIT();
    for (int kt = 0; kt < nkt; ++kt) {
        if (kt + 1 < nkt) load_stage((kt + 1) & 1, (kt + 1) * GBK);
        CP_COMMIT();
        CP_WAIT1();
        __syncthreads();
        const __nv_bfloat16* base = sm + (kt & 1) * GSTAGE;
        const __nv_bfloat16* sAh = base;
        const __nv_bfloat16* sAl = base + GARR;
        const __nv_bfloat16* sBh = base + 2 * GARR;
        const __nv_bfloat16* sBl = base + 3 * GARR;
        #pragma unroll
        for (int ks = 0; ks < 2; ++ks) {
            int k0 = ks * 16;
            u32 ah[2][4], al[2][4];
            #pragma unroll
            for (int mt = 0; mt < 2; ++mt) {
                int r0 = wm * 32 + mt * 16 + a_row;
                ldsm4(ah[mt][0], ah[mt][1], ah[mt][2], ah[mt][3], sAh + r0 * GPK + k0 + a_col);
                ldsm4(al[mt][0], al[mt][1], al[mt][2], al[mt][3], sAl + r0 * GPK + k0 + a_col);
            }
            #pragma unroll
            for (int np = 0; np < 4; ++np) {
                int n0 = wn * 64 + np * 16 + b_row;
                u32 bh[4], bl[4];
                ldsm4(bh[0], bh[1], bh[2], bh[3], sBh + n0 * GPK + k0 + b_col);
                ldsm4(bl[0], bl[1], bl[2], bl[3], sBl + n0 * GPK + k0 + b_col);
                #pragma unroll
                for (int mt = 0; mt < 2; ++mt) {
                    mma16816(acc[mt][2*np],   ah[mt], bh);
                    mma16816(acc[mt][2*np],   ah[mt], bl);
                    mma16816(acc[mt][2*np],   al[mt], bh);
                    mma16816(acc[mt][2*np+1], ah[mt], bh + 2);
                    mma16816(acc[mt][2*np+1], ah[mt], bl + 2);
                    mma16816(acc[mt][2*np+1], al[mt], bh + 2);
                }
            }
        }
        __syncthreads();
    }

    #pragma unroll
    for (int mt = 0; mt < 2; ++mt)
        #pragma unroll
        for (int nt = 0; nt < 8; ++nt) {
            int row = bm + wm * 32 + mt * 16 + g;
            int col = bn + wn * 64 + nt * 8 + 2 * tg;
            if (OutHi) {
                u32 h0, l0, h1, l1;
                split_pack(alpha * acc[mt][nt][0], alpha * acc[mt][nt][1], h0, l0);
                split_pack(alpha * acc[mt][nt][2], alpha * acc[mt][nt][3], h1, l1);
                size_t i0 = ((size_t)row * N + col) >> 1;
                size_t i1 = ((size_t)(row + 8) * N + col) >> 1;
                ((u32*)OutHi)[i0] = h0; ((u32*)OutLo)[i0] = l0;
                ((u32*)OutHi)[i1] = h1; ((u32*)OutLo)[i1] = l1;
            } else {
                float* p0 = C + (size_t)row * N + col;
                float* p1 = C + (size_t)(row + 8) * N + col;
                if (beta) {
                    p0[0] += alpha * acc[mt][nt][0];
                    p0[1] += alpha * acc[mt][nt][1];
                    p1[0] += alpha * acc[mt][nt][2];
                    p1[1] += alpha * acc[mt][nt][3];
                } else {
                    p0[0] = alpha * acc[mt][nt][0];
                    p0[1] = alpha * acc[mt][nt][1];
                    p1[0] = alpha * acc[mt][nt][2];
                    p1[1] = alpha * acc[mt][nt][3];
                }
            }
        }
}

// ---------------- RoPE + split + scatter to [b,h,s,d] ----------------
__global__ void __launch_bounds__(256) rope_split(
    const float* __restrict__ qkv, const int* __restrict__ pos_ids,
    __nv_bfloat16* __restrict__ Qh, __nv_bfloat16* __restrict__ Ql,
    __nv_bfloat16* __restrict__ Kh, __nv_bfloat16* __restrict__ Kl,
    __nv_bfloat16* __restrict__ Vh, __nv_bfloat16* __restrict__ Vl)
{
    int bs = blockIdx.x;
    int b = bs / SS, s = bs % SS;
    __shared__ float cosv[ROTD], sinv[ROTD];
    int tid = threadIdx.x;
    if (tid < 48) {
        float invf = (float)pow(10000.0, -(double)tid / 48.0);
        float ang = (float)pos_ids[bs] * invf;
        float c = (float)cos((double)ang), sn = (float)sin((double)ang);
        cosv[tid] = c; cosv[tid + 48] = c;
        sinv[tid] = sn; sinv[tid + 48] = sn;
    }
    __syncthreads();
    const float* src = qkv + (size_t)bs * OPSZ;
    for (int e = tid; e < OPSZ; e += 256) {
        int d = e & 127;
        int hh = e >> 7;
        float v = src[e];
        bool isq = hh < NHEADS;
        bool isk = (hh >= NHEADS) && (hh < NHEADS + NKV);
        float outv = v;
        if ((isq || isk) && d < ROTD) {
            if (d < 48) outv = v * cosv[d] - src[e + 48] * sinv[d];
            else        outv = v * cosv[d] + src[e - 48] * sinv[d];
        }
        __nv_bfloat16 hi = __float2bfloat16(outv);
        __nv_bfloat16 lo = __float2bfloat16(outv - __bfloat162float(hi));
        if (isq) {
            size_t dst = ((size_t)(b * NHEADS + hh) * SS + s) * HD + d;
            Qh[dst] = hi; Ql[dst] = lo;
        } else if (isk) {
            size_t dst = ((size_t)(b * NKV + (hh - NHEADS)) * SS + s) * HD + d;
            Kh[dst] = hi; Kl[dst] = lo;
        } else {
            size_t dst = ((size_t)(b * NKV + (hh - NHEADS - NKV)) * SS + s) * HD + d;
            Vh[dst] = hi; Vl[dst] = lo;
        }
    }
}

// ---------------- causal flash attention (GQA), split-bf16, ldmatrix ----------------
#define FQP 136

__global__ void __launch_bounds__(128) flash_attn(
    const __nv_bfloat16* __restrict__ Qh, const __nv_bfloat16* __restrict__ Ql,
    const __nv_bfloat16* __restrict__ Kh, const __nv_bfloat16* __restrict__ Kl,
    const __nv_bfloat16* __restrict__ Vh, const __nv_bfloat16* __restrict__ Vl,
    __nv_bfloat16* __restrict__ AtH, __nv_bfloat16* __restrict__ AtL)
{
    extern __shared__ __nv_bfloat16 fsm[];
    __nv_bfloat16* sQh = fsm;
    __nv_bfloat16* sQl = fsm + 1 * 64 * FQP;
    __nv_bfloat16* sKh = fsm + 2 * 64 * FQP;
    __nv_bfloat16* sKl = fsm + 3 * 64 * FQP;
    __nv_bfloat16* sVh = fsm + 4 * 64 * FQP;
    __nv_bfloat16* sVl = fsm + 5 * 64 * FQP;

    int qt = blockIdx.x, h = blockIdx.y, b = blockIdx.z;
    int kvh = h / (NHEADS / NKV);
    int tid = threadIdx.x, warp = tid >> 5, lane = tid & 31;
    int g = lane >> 2, tg = lane & 3;

    // ldmatrix lane address components
    int a_row = warp * 16 + (lane & 15);
    int a_col = (lane >> 4) << 3;
    int b_row = (lane & 7) + ((lane >> 4) << 3);
    int b_col = ((lane >> 3) & 1) << 3;
    int v_row = (lane & 7) + (((lane >> 3) & 1) << 3);
    int v_col = ((lane >> 4) & 1) << 3;

    size_t qbase = ((size_t)(b * NHEADS + h) * SS + (size_t)qt * 64) * HD;
    #pragma unroll
    for (int i = 0; i < 8; ++i) {
        int task = tid + i * 128;
        int row = task >> 4, ch = task & 15;
        cp_async16(sQh + row * FQP + ch * 8, Qh + qbase + row * HD + ch * 8);
        cp_async16(sQl + row * FQP + ch * 8, Ql + qbase + row * HD + ch * 8);
    }
    CP_COMMIT();

    float m0 = -1e30f, m1 = -1e30f, l0 = 0.f, l1 = 0.f;
    float oacc[16][4];
    #pragma unroll
    for (int i = 0; i < 16; ++i)
        #pragma unroll
        for (int r = 0; r < 4; ++r) oacc[i][r] = 0.f;

    for (int kt = 0; kt <= qt; ++kt) {
        size_t kbase = ((size_t)(b * NKV + kvh) * SS + (size_t)kt * 64) * HD;
        #pragma unroll
        for (int i = 0; i < 8; ++i) {
            int task = tid + i * 128;
            int row = task >> 4, ch = task & 15;
            cp_async16(sKh + row * FQP + ch * 8, Kh + kbase + row * HD + ch * 8);
            cp_async16(sKl + row * FQP + ch * 8, Kl + kbase + row * HD + ch * 8);
            cp_async16(sVh + row * FQP + ch * 8, Vh + kbase + row * HD + ch * 8);
            cp_async16(sVl + row * FQP + ch * 8, Vl + kbase + row * HD + ch * 8);
        }
        CP_COMMIT();
        CP_WAIT0();
        __syncthreads();

        // S = Q K^T
        float sacc[8][4];
        #pragma unroll
        for (int nt = 0; nt < 8; ++nt)
            #pragma unroll
            for (int r = 0; r < 4; ++r) sacc[nt][r] = 0.f;

        #pragma unroll
        for (int kc = 0; kc < 8; ++kc) {
            int k0 = kc * 16;
            u32 ah[4], al[4];
            ldsm4(ah[0], ah[1], ah[2], ah[3], sQh + a_row * FQP + k0 + a_col);
            ldsm4(al[0], al[1], al[2], al[3], sQl + a_row * FQP + k0 + a_col);
            #pragma unroll
            for (int np = 0; np < 4; ++np) {
                int n0 = np * 16 + b_row;
                u32 bh[4], bl[4];
                ldsm4(bh[0], bh[1], bh[2], bh[3], sKh + n0 * FQP + k0 + b_col);
                ldsm4(bl[0], bl[1], bl[2], bl[3], sKl + n0 * FQP + k0 + b_col);
                mma16816(sacc[2*np],   ah, bh);
                mma16816(sacc[2*np],   ah, bl);
                mma16816(sacc[2*np],   al, bh);
                mma16816(sacc[2*np+1], ah, bh + 2);
                mma16816(sacc[2*np+1], ah, bl + 2);
                mma16816(sacc[2*np+1], al, bh + 2);
            }
        }

        bool diag = (kt == qt);
        int row0 = qt * 64 + warp * 16 + g;
        #pragma unroll
        for (int nt = 0; nt < 8; ++nt)
            #pragma unroll
            for (int r = 0; r < 4; ++r) {
                float v = sacc[nt][r] * ATT_SCALE;
                if (diag) {
                    int col = kt * 64 + nt * 8 + 2 * tg + (r & 1);
                    int row = row0 + ((r >= 2) ? 8 : 0);
                    if (col > row) v = -1e30f;
                }
                sacc[nt][r] = v;
            }

        float rm0 = -1e30f, rm1 = -1e30f;
        #pragma unroll
        for (int nt = 0; nt < 8; ++nt) {
            rm0 = fmaxf(rm0, fmaxf(sacc[nt][0], sacc[nt][1]));
            rm1 = fmaxf(rm1, fmaxf(sacc[nt][2], sacc[nt][3]));
        }
        rm0 = fmaxf(rm0, __shfl_xor_sync(0xffffffffu, rm0, 1));
        rm0 = fmaxf(rm0, __shfl_xor_sync(0xffffffffu, rm0, 2));
        rm1 = fmaxf(rm1, __shfl_xor_sync(0xffffffffu, rm1, 1));
        rm1 = fmaxf(rm1, __shfl_xor_sync(0xffffffffu, rm1, 2));
        float nm0 = fmaxf(m0, rm0), nm1 = fmaxf(m1, rm1);
        float alpha0 = __expf(m0 - nm0), alpha1 = __expf(m1 - nm1);
        m0 = nm0; m1 = nm1;
        float rs0 = 0.f, rs1 = 0.f;
        #pragma unroll
        for (int nt = 0; nt < 8; ++nt) {
            sacc[nt][0] = __expf(sacc[nt][0] - m0); rs0 += sacc[nt][0];
            sacc[nt][1] = __expf(sacc[nt][1] - m0); rs0 += sacc[nt][1];
            sacc[nt][2] = __expf(sacc[nt][2] - m1); rs1 += sacc[nt][2];
            sacc[nt][3] = __expf(sacc[nt][3] - m1); rs1 += sacc[nt][3];
        }
        rs0 += __shfl_xor_sync(0xffffffffu, rs0, 1);
        rs0 += __shfl_xor_sync(0xffffffffu, rs0, 2);
        rs1 += __shfl_xor_sync(0xffffffffu, rs1, 1);
        rs1 += __shfl_xor_sync(0xffffffffu, rs1, 2);
        l0 = l0 * alpha0 + rs0;
        l1 = l1 * alpha1 + rs1;
        #pragma unroll
        for (int nt = 0; nt < 16; ++nt) {
            oacc[nt][0] *= alpha0; oacc[nt][1] *= alpha0;
            oacc[nt][2] *= alpha1; oacc[nt][3] *= alpha1;
        }

        // O += P V   (V via ldmatrix.trans, natural [kv][d] layout)
        #pragma unroll
        for (int kc2 = 0; kc2 < 4; ++kc2) {
            int kv0 = kc2 * 16;
            u32 ph4[4], pl4[4];
            split_pack(sacc[2*kc2][0],   sacc[2*kc2][1],   ph4[0], pl4[0]);
            split_pack(sacc[2*kc2][2],   sacc[2*kc2][3],   ph4[1], pl4[1]);
            split_pack(sacc[2*kc2+1][0], sacc[2*kc2+1][1], ph4[2], pl4[2]);
            split_pack(sacc[2*kc2+1][2], sacc[2*kc2+1][3], ph4[3], pl4[3]);
            #pragma unroll
            for (int np = 0; np < 8; ++np) {
                int d0 = np * 16 + v_col;
                u32 bh[4], bl[4];
                ldsm4t(bh[0], bh[1], bh[2], bh[3], sVh + (kv0 + v_row) * FQP + d0);
                ldsm4t(bl[0], bl[1], bl[2], bl[3], sVl + (kv0 + v_row) * FQP + d0);
                mma16816(oacc[2*np],   ph4, bh);
                mma16816(oacc[2*np],   ph4, bl);
                mma16816(oacc[2*np],   pl4, bh);
                mma16816(oacc[2*np+1], ph4, bh + 2);
                mma16816(oacc[2*np+1], ph4, bl + 2);
                mma16816(oacc[2*np+1], pl4, bh + 2);
            }
        }
        __syncthreads();
    }

    float inv0 = 1.f / l0, inv1 = 1.f / l1;
    int srow = qt * 64 + warp * 16 + g;
    #pragma unroll
    for (int nt = 0; nt < 16; ++nt) {
        int col = nt * 8 + 2 * tg;
        float a0 = oacc[nt][0] * inv0, a1 = oacc[nt][1] * inv0;
        float a2 = oacc[nt][2] * inv1, a3 = oacc[nt][3] * inv1;
        u32 h0, L0, h1, L1;
        split_pack(a0, a1, h0, L0);
        split_pack(a2, a3, h1, L1);
        size_t e0 = ((size_t)(b * SS + srow) * HIDDEN + h * HD + col) >> 1;
        size_t e1 = ((size_t)(b * SS + srow + 8) * HIDDEN + h * HD + col) >> 1;
        ((u32*)AtH)[e0] = h0; ((u32*)AtL)[e0] = L0;
        ((u32*)AtH)[e1] = h1; ((u32*)AtL)[e1] = L1;
    }
}

// ---------------- launch ----------------
static inline void do_split(const float* src, unsigned char* heap, size_t ohi, size_t olo, size_t n) {
    size_t n4 = n / 4;
    split_fp32<<<(unsigned)((n4 + 255) / 256), 256>>>(
        src, (__nv_bfloat16*)(heap + ohi), (__nv_bfloat16*)(heap + olo), n4);
}

extern "C" void kernel_launch(void* const* d_in, const int* in_sizes, int n_in,
                              void* d_out, int out_size) {
    const float* x    = (const float*)d_in[0];
    const float* Wqkv = (const float*)d_in[1];
    const float* Aqkv = (const float*)d_in[2];
    const float* Bqkv = (const float*)d_in[3];
    const float* Wo   = (const float*)d_in[4];
    const float* Ao   = (const float*)d_in[5];
    const float* Bo   = (const float*)d_in[6];
    const int*   pos  = (const int*)d_in[7];
    float* out = (float*)d_out;

    unsigned char* heap = nullptr;
    cudaGetSymbolAddress((void**)&heap, g_heap);

    size_t gemm_smem  = 2 * GSTAGE * sizeof(__nv_bfloat16);
    size_t flash_smem = 6 * 64 * FQP * sizeof(__nv_bfloat16);
    cudaFuncSetAttribute(gemm_split, cudaFuncAttributeMaxDynamicSharedMemorySize, (int)gemm_smem);
    cudaFuncSetAttribute(flash_attn, cudaFuncAttributeMaxDynamicSharedMemorySize, (int)flash_smem);

#define BF(off) ((__nv_bfloat16*)(heap + off))
#define FP(off) ((float*)(heap + off))

    // split inputs
    do_split(x,    heap, O_XHI, O_XLO, SZ_X);
    do_split(Wqkv, heap, O_WQH, O_WQL, SZ_WQKV);
    do_split(Aqkv, heap, O_AQH, O_AQL, SZ_AQ);
    do_split(Bqkv, heap, O_BQH, O_BQL, SZ_BQ);
    do_split(Wo,   heap, O_WOH, O_WOL, SZ_WO);
    do_split(Ao,   heap, O_AOH, O_AOL, SZ_AQ);
    do_split(Bo,   heap, O_BOH, O_BOL, SZ_BO);

    // QKV = x @ Wqkv^T   (fp32)
    gemm_split<<<dim3(OPSZ / 128, MTOT / 128), 256, gemm_smem>>>(
        BF(O_XHI), BF(O_XLO), BF(O_WQH), BF(O_WQL), FP(O_QKV),
        nullptr, nullptr, MTOT, OPSZ, HIDDEN, 1.0f, 0);
    // T1 = x @ Aqkv^T    (hi/lo direct)
    gemm_split<<<dim3(RLORA / 128, MTOT / 128), 256, gemm_smem>>>(
        BF(O_XHI), BF(O_XLO), BF(O_AQH), BF(O_AQL), nullptr,
        BF(O_T1H), BF(O_T1L), MTOT, RLORA, HIDDEN, 1.0f, 0);
    // QKV += LORA_SC * T1 @ Bqkv^T
    gemm_split<<<dim3(OPSZ / 128, MTOT / 128), 256, gemm_smem>>>(
        BF(O_T1H), BF(O_T1L), BF(O_BQH), BF(O_BQL), FP(O_QKV),
        nullptr, nullptr, MTOT, OPSZ, RLORA, LORA_SC, 1);

    // RoPE + scatter + split
    rope_split<<<MTOT, 256>>>(FP(O_QKV), pos,
        BF(O_QH), BF(O_QL), BF(O_KH), BF(O_KL), BF(O_VH), BF(O_VL));

    // flash attention (writes hi/lo attn directly)
    flash_attn<<<dim3(SS / 64, NHEADS, BB), 128, flash_smem>>>(
        BF(O_QH), BF(O_QL), BF(O_KH), BF(O_KL), BF(O_VH), BF(O_VL),
        BF(O_ATH), BF(O_ATL));

    // out = attn @ Wo^T
    gemm_split<<<dim3(HIDDEN / 128, MTOT / 128), 256, gemm_smem>>>(
        BF(O_ATH), BF(O_ATL), BF(O_WOH), BF(O_WOL), out,
        nullptr, nullptr, MTOT, HIDDEN, HIDDEN, 1.0f, 0);
    // T2 = attn @ Ao^T   (hi/lo direct)
    gemm_split<<<dim3(RLORA / 128, MTOT / 128), 256, gemm_smem>>>(
        BF(O_ATH), BF(O_ATL), BF(O_AOH), BF(O_AOL), nullptr,
        BF(O_T2H), BF(O_T2L), MTOT, RLORA, HIDDEN, 1.0f, 0);
    // out += LORA_SC * T2 @ Bo^T
    gemm_split<<<dim3(HIDDEN / 128, MTOT / 128), 256, gemm_smem>>>(
        BF(O_T2H), BF(O_T2L), BF(O_BOH), BF(O_BOL), out,
        nullptr, nullptr, MTOT, HIDDEN, RLORA, LORA_SC, 1);

#undef BF
#undef FP
}

// round 7
// speedup vs baseline: 1.9666x; 1.4421x over previous
#include <cuda_runtime.h>
#include <cuda_fp16.h>
#include <cstdint>
#include <cmath>

#define HIDDEN 3072
#define NHEADS 24
#define NKV 8
#define HD 128
#define ROTD 96
#define OPSZ 5120
#define RLORA 256
#define BB 2
#define SS 2048
#define MTOT (BB*SS)
#define ATT_SCALE 0.08838834764831845f
#define LORA_SC 2.0f

typedef unsigned int u32;

// ---------------- static scratch heap ----------------
constexpr size_t SZ_X    = (size_t)MTOT*HIDDEN;
constexpr size_t SZ_WQKV = (size_t)OPSZ*HIDDEN;
constexpr size_t SZ_AQ   = (size_t)RLORA*HIDDEN;
constexpr size_t SZ_BQ   = (size_t)OPSZ*RLORA;
constexpr size_t SZ_WO   = (size_t)HIDDEN*HIDDEN;
constexpr size_t SZ_BO   = (size_t)HIDDEN*RLORA;
constexpr size_t SZ_QKV  = (size_t)MTOT*OPSZ;
constexpr size_t SZ_T    = (size_t)MTOT*RLORA;
constexpr size_t SZ_Q    = (size_t)BB*NHEADS*SS*HD;
constexpr size_t SZ_KV   = (size_t)BB*NKV*SS*HD;

constexpr size_t al256(size_t x){ return (x+255)&~(size_t)255; }

constexpr size_t O_XHI = 0;
constexpr size_t O_XLO = O_XHI + al256(SZ_X*2);
constexpr size_t O_WQH = O_XLO + al256(SZ_X*2);
constexpr size_t O_AQH = O_WQH + al256(SZ_WQKV*2);
constexpr size_t O_BQH = O_AQH + al256(SZ_AQ*2);
constexpr size_t O_WOH = O_BQH + al256(SZ_BQ*2);
constexpr size_t O_AOH = O_WOH + al256(SZ_WO*2);
constexpr size_t O_BOH = O_AOH + al256(SZ_AQ*2);
constexpr size_t O_T1H = O_BOH + al256(SZ_BO*2);
constexpr size_t O_T1L = O_T1H + al256(SZ_T*2);
constexpr size_t O_T2H = O_T1L + al256(SZ_T*2);
constexpr size_t O_T2L = O_T2H + al256(SZ_T*2);
constexpr size_t O_QH  = O_T2L + al256(SZ_T*2);
constexpr size_t O_QL  = O_QH  + al256(SZ_Q*2);
constexpr size_t O_KH  = O_QL  + al256(SZ_Q*2);
constexpr size_t O_VH  = O_KH  + al256(SZ_KV*2);
constexpr size_t O_ATH = O_VH  + al256(SZ_KV*2);
constexpr size_t O_ATL = O_ATH + al256(SZ_X*2);
constexpr size_t O_QKV = O_ATL + al256(SZ_X*2);
constexpr size_t HEAP_BYTES = O_QKV + al256(SZ_QKV*4);

__device__ __align__(256) unsigned char g_heap[HEAP_BYTES];

// ---------------- helpers ----------------
__device__ __forceinline__ void mma16816(float* c, const u32* a, const u32* b) {
    asm volatile("mma.sync.aligned.m16n8k16.row.col.f32.f16.f16.f32 "
        "{%0,%1,%2,%3}, {%4,%5,%6,%7}, {%8,%9}, {%0,%1,%2,%3};\n"
        : "+f"(c[0]), "+f"(c[1]), "+f"(c[2]), "+f"(c[3])
        : "r"(a[0]), "r"(a[1]), "r"(a[2]), "r"(a[3]), "r"(b[0]), "r"(b[1]));
}
__device__ __forceinline__ void cp_async16(void* smem, const void* g) {
    u32 sa = (u32)__cvta_generic_to_shared(smem);
    asm volatile("cp.async.cg.shared.global [%0], [%1], 16;\n" :: "r"(sa), "l"(g));
}
#define CP_COMMIT() asm volatile("cp.async.commit_group;\n")
#define CP_WAIT1()  asm volatile("cp.async.wait_group 1;\n")
#define CP_WAIT0()  asm volatile("cp.async.wait_group 0;\n")

__device__ __forceinline__ void ldsm4(u32& r0, u32& r1, u32& r2, u32& r3, const __half* p) {
    u32 a = (u32)__cvta_generic_to_shared(p);
    asm volatile("ldmatrix.sync.aligned.m8n8.x4.shared.b16 {%0,%1,%2,%3}, [%4];\n"
        : "=r"(r0), "=r"(r1), "=r"(r2), "=r"(r3) : "r"(a));
}
__device__ __forceinline__ void ldsm4t(u32& r0, u32& r1, u32& r2, u32& r3, const __half* p) {
    u32 a = (u32)__cvta_generic_to_shared(p);
    asm volatile("ldmatrix.sync.aligned.m8n8.x4.trans.shared.b16 {%0,%1,%2,%3}, [%4];\n"
        : "=r"(r0), "=r"(r1), "=r"(r2), "=r"(r3) : "r"(a));
}

__device__ __forceinline__ void split_pack(float x, float y, u32& hi, u32& lo) {
    __half hx = __float2half_rn(x);
    __half hy = __float2half_rn(y);
    __half lx = __float2half_rn(x - __half2float(hx));
    __half ly = __float2half_rn(y - __half2float(hy));
    hi = ((u32)__half_as_ushort(hy) << 16) | (u32)__half_as_ushort(hx);
    lo = ((u32)__half_as_ushort(ly) << 16) | (u32)__half_as_ushort(lx);
}
__device__ __forceinline__ u32 pack_h2(float x, float y) {
    __half hx = __float2half_rn(x);
    __half hy = __float2half_rn(y);
    return ((u32)__half_as_ushort(hy) << 16) | (u32)__half_as_ushort(hx);
}

// ---------------- fp32 -> fp16 hi/lo split ----------------
__global__ void split_fp32(const float* __restrict__ in,
                           __half* __restrict__ hi,
                           __half* __restrict__ lo, size_t n4) {
    size_t i = (size_t)blockIdx.x * blockDim.x + threadIdx.x;
    if (i >= n4) return;
    float4 v = ((const float4*)in)[i];
    u32 h0, l0, h1, l1;
    split_pack(v.x, v.y, h0, l0);
    split_pack(v.z, v.w, h1, l1);
    ((uint2*)hi)[i] = make_uint2(h0, h1);
    ((uint2*)lo)[i] = make_uint2(l0, l1);
}

// ---------------- fp32 -> fp16 (hi only, for B operands) ----------------
__global__ void conv_fp16(const float* __restrict__ in, __half* __restrict__ hi, size_t n4) {
    size_t i = (size_t)blockIdx.x * blockDim.x + threadIdx.x;
    if (i >= n4) return;
    float4 v = ((const float4*)in)[i];
    ((uint2*)hi)[i] = make_uint2(pack_h2(v.x, v.y), pack_h2(v.z, v.w));
}

// ---------------- GEMM: C[M,N] = alpha * [A1|A2][M,K1+K2] @ ([B1|B2][N,K1+K2])^T ----------------
// A split hi/lo fp16 (2-pass), B fp16 hi only. If Oh != nullptr writes split hi/lo fp16.
#define GBK 32
#define GPK 40
#define GARR (128*GPK)
#define GSTAGE (3*GARR)

__global__ void __launch_bounds__(256, 2) gemm_split(
    const __half* __restrict__ A1h, const __half* __restrict__ A1l,
    const __half* __restrict__ A2h, const __half* __restrict__ A2l,
    const __half* __restrict__ B1h, const __half* __restrict__ B2h,
    float* __restrict__ C,
    __half* __restrict__ Oh, __half* __restrict__ Ol,
    int N, int K1, int K2, float alpha)
{
    extern __shared__ __half sm[];
    int tid = threadIdx.x;
    int bm = blockIdx.y * 128, bn = blockIdx.x * 128;
    int warp = tid >> 5, lane = tid & 31;
    int wm = warp >> 1, wn = warp & 1;
    int g = lane >> 2, tg = lane & 3;

    auto load_stage = [&](int c) {
        int stage = c & 1;
        __half* base = sm + stage * GSTAGE;
        int k0 = c * GBK;
        bool s2 = (k0 >= K1);
        int koff = s2 ? (k0 - K1) : k0;
        int sk = s2 ? K2 : K1;
        const __half* ah = (s2 ? A2h : A1h) + koff;
        const __half* al = (s2 ? A2l : A1l) + koff;
        const __half* bh = (s2 ? B2h : B1h) + koff;
        #pragma unroll
        for (int i = 0; i < 6; ++i) {
            int task = tid + i * 256;
            int arr = task >> 9;
            int rem = task & 511;
            int row = rem >> 2;
            int ch  = rem & 3;
            const __half* gsrc;
            if (arr == 0)      gsrc = ah + (size_t)(bm + row) * sk + ch * 8;
            else if (arr == 1) gsrc = al + (size_t)(bm + row) * sk + ch * 8;
            else               gsrc = bh + (size_t)(bn + row) * sk + ch * 8;
            cp_async16(base + arr * GARR + row * GPK + ch * 8, gsrc);
        }
        CP_COMMIT();
    };

    float acc[2][8][4];
    #pragma unroll
    for (int a = 0; a < 2; ++a)
        #pragma unroll
        for (int b = 0; b < 8; ++b)
            #pragma unroll
            for (int c = 0; c < 4; ++c) acc[a][b][c] = 0.f;

    int a_row = lane & 15;
    int a_col = (lane >> 4) << 3;
    int b_row = (lane & 7) + ((lane >> 4) << 3);
    int b_col = ((lane >> 3) & 1) << 3;

    int nkt = (K1 + K2) / GBK;
    load_stage(0);
    for (int kt = 0; kt < nkt; ++kt) {
        if (kt + 1 < nkt) load_stage(kt + 1); else CP_COMMIT();
        CP_WAIT1();
        __syncthreads();
        const __half* base = sm + (kt & 1) * GSTAGE;
        const __half* sAh = base;
        const __half* sAl = base + GARR;
        const __half* sBh = base + 2 * GARR;
        #pragma unroll
        for (int ks = 0; ks < 2; ++ks) {
            int k0 = ks * 16;
            u32 ah[2][4], al[2][4];
            #pragma unroll
            for (int mt = 0; mt < 2; ++mt) {
                int r0 = wm * 32 + mt * 16 + a_row;
                ldsm4(ah[mt][0], ah[mt][1], ah[mt][2], ah[mt][3], sAh + r0 * GPK + k0 + a_col);
                ldsm4(al[mt][0], al[mt][1], al[mt][2], al[mt][3], sAl + r0 * GPK + k0 + a_col);
            }
            #pragma unroll
            for (int np = 0; np < 4; ++np) {
                int n0 = wn * 64 + np * 16 + b_row;
                u32 bh[4];
                ldsm4(bh[0], bh[1], bh[2], bh[3], sBh + n0 * GPK + k0 + b_col);
                #pragma unroll
                for (int mt = 0; mt < 2; ++mt) {
                    mma16816(acc[mt][2*np],   ah[mt], bh);
                    mma16816(acc[mt][2*np],   al[mt], bh);
                    mma16816(acc[mt][2*np+1], ah[mt], bh + 2);
                    mma16816(acc[mt][2*np+1], al[mt], bh + 2);
                }
            }
        }
        __syncthreads();
    }

    #pragma unroll
    for (int mt = 0; mt < 2; ++mt)
        #pragma unroll
        for (int nt = 0; nt < 8; ++nt) {
            int row = bm + wm * 32 + mt * 16 + g;
            int col = bn + wn * 64 + nt * 8 + 2 * tg;
            float v0 = alpha * acc[mt][nt][0], v1 = alpha * acc[mt][nt][1];
            float v2 = alpha * acc[mt][nt][2], v3 = alpha * acc[mt][nt][3];
            if (Oh) {
                u32 h0, l0, h1, l1;
                split_pack(v0, v1, h0, l0);
                split_pack(v2, v3, h1, l1);
                size_t i0 = ((size_t)row * N + col) >> 1;
                size_t i1 = ((size_t)(row + 8) * N + col) >> 1;
                ((u32*)Oh)[i0] = h0; ((u32*)Ol)[i0] = l0;
                ((u32*)Oh)[i1] = h1; ((u32*)Ol)[i1] = l1;
            } else {
                float* p0 = C + (size_t)row * N + col;
                float* p1 = C + (size_t)(row + 8) * N + col;
                p0[0] = v0; p0[1] = v1;
                p1[0] = v2; p1[1] = v3;
            }
        }
}

// ---------------- RoPE + split + scatter to [b,h,s,d] ----------------
// Q -> hi/lo (split A-operand); K, V -> hi only (B-operands).
__global__ void __launch_bounds__(256) rope_split(
    const float* __restrict__ qkv, const int* __restrict__ pos_ids,
    __half* __restrict__ Qh, __half* __restrict__ Ql,
    __half* __restrict__ Kh, __half* __restrict__ Vh)
{
    int bs = blockIdx.x;
    int b = bs / SS, s = bs % SS;
    __shared__ float cosv[ROTD], sinv[ROTD];
    int tid = threadIdx.x;
    if (tid < 48) {
        float invf = (float)pow(10000.0, -(double)tid / 48.0);
        float ang = (float)pos_ids[bs] * invf;
        float c = (float)cos((double)ang), sn = (float)sin((double)ang);
        cosv[tid] = c; cosv[tid + 48] = c;
        sinv[tid] = sn; sinv[tid + 48] = sn;
    }
    __syncthreads();
    const float* src = qkv + (size_t)bs * OPSZ;
    for (int e = tid; e < OPSZ; e += 256) {
        int d = e & 127;
        int hh = e >> 7;
        float v = src[e];
        bool isq = hh < NHEADS;
        bool isk = (hh >= NHEADS) && (hh < NHEADS + NKV);
        float outv = v;
        if ((isq || isk) && d < ROTD) {
            if (d < 48) outv = v * cosv[d] - src[e + 48] * sinv[d];
            else        outv = v * cosv[d] + src[e - 48] * sinv[d];
        }
        if (isq) {
            __half hi = __float2half_rn(outv);
            __half lo = __float2half_rn(outv - __half2float(hi));
            size_t dst = ((size_t)(b * NHEADS + hh) * SS + s) * HD + d;
            Qh[dst] = hi; Ql[dst] = lo;
        } else if (isk) {
            size_t dst = ((size_t)(b * NKV + (hh - NHEADS)) * SS + s) * HD + d;
            Kh[dst] = __float2half_rn(outv);
        } else {
            size_t dst = ((size_t)(b * NKV + (hh - NHEADS - NKV)) * SS + s) * HD + d;
            Vh[dst] = __float2half_rn(outv);
        }
    }
}

// ---------------- causal flash attention (GQA), fp16 2-pass, ldmatrix ----------------
#define FQP 136

__global__ void __launch_bounds__(128) flash_attn(
    const __half* __restrict__ Qh, const __half* __restrict__ Ql,
    const __half* __restrict__ Kh, const __half* __restrict__ Vh,
    __half* __restrict__ AtH, __half* __restrict__ AtL)
{
    extern __shared__ __half fsm[];
    __half* sQh = fsm;
    __half* sQl = fsm + 1 * 64 * FQP;
    __half* sKh = fsm + 2 * 64 * FQP;
    __half* sVh = fsm + 3 * 64 * FQP;

    int qt = blockIdx.x, h = blockIdx.y, b = blockIdx.z;
    int kvh = h / (NHEADS / NKV);
    int tid = threadIdx.x, warp = tid >> 5, lane = tid & 31;
    int g = lane >> 2, tg = lane & 3;

    int a_row = warp * 16 + (lane & 15);
    int a_col = (lane >> 4) << 3;
    int b_row = (lane & 7) + ((lane >> 4) << 3);
    int b_col = ((lane >> 3) & 1) << 3;
    int v_row = (lane & 7) + (((lane >> 3) & 1) << 3);
    int v_col = ((lane >> 4) & 1) << 3;

    size_t qbase = ((size_t)(b * NHEADS + h) * SS + (size_t)qt * 64) * HD;
    #pragma unroll
    for (int i = 0; i < 8; ++i) {
        int task = tid + i * 128;
        int row = task >> 4, ch = task & 15;
        cp_async16(sQh + row * FQP + ch * 8, Qh + qbase + row * HD + ch * 8);
        cp_async16(sQl + row * FQP + ch * 8, Ql + qbase + row * HD + ch * 8);
    }
    CP_COMMIT();

    float m0 = -1e30f, m1 = -1e30f, l0 = 0.f, l1 = 0.f;
    float oacc[16][4];
    #pragma unroll
    for (int i = 0; i < 16; ++i)
        #pragma unroll
        for (int r = 0; r < 4; ++r) oacc[i][r] = 0.f;

    for (int kt = 0; kt <= qt; ++kt) {
        size_t kbase = ((size_t)(b * NKV + kvh) * SS + (size_t)kt * 64) * HD;
        #pragma unroll
        for (int i = 0; i < 8; ++i) {
            int task = tid + i * 128;
            int row = task >> 4, ch = task & 15;
            cp_async16(sKh + row * FQP + ch * 8, Kh + kbase + row * HD + ch * 8);
            cp_async16(sVh + row * FQP + ch * 8, Vh + kbase + row * HD + ch * 8);
        }
        CP_COMMIT();
        CP_WAIT0();
        __syncthreads();

        float sacc[8][4];
        #pragma unroll
        for (int nt = 0; nt < 8; ++nt)
            #pragma unroll
            for (int r = 0; r < 4; ++r) sacc[nt][r] = 0.f;

        #pragma unroll
        for (int kc = 0; kc < 8; ++kc) {
            int k0 = kc * 16;
            u32 ah[4], al[4];
            ldsm4(ah[0], ah[1], ah[2], ah[3], sQh + a_row * FQP + k0 + a_col);
            ldsm4(al[0], al[1], al[2], al[3], sQl + a_row * FQP + k0 + a_col);
            #pragma unroll
            for (int np = 0; np < 4; ++np) {
                int n0 = np * 16 + b_row;
                u32 bh[4];
                ldsm4(bh[0], bh[1], bh[2], bh[3], sKh + n0 * FQP + k0 + b_col);
                mma16816(sacc[2*np],   ah, bh);
                mma16816(sacc[2*np],   al, bh);
                mma16816(sacc[2*np+1], ah, bh + 2);
                mma16816(sacc[2*np+1], al, bh + 2);
            }
        }

        bool diag = (kt == qt);
        int row0 = qt * 64 + warp * 16 + g;
        #pragma unroll
        for (int nt = 0; nt < 8; ++nt)
            #pragma unroll
            for (int r = 0; r < 4; ++r) {
                float v = sacc[nt][r] * ATT_SCALE;
                if (diag) {
                    int col = kt * 64 + nt * 8 + 2 * tg + (r & 1);
                    int row = row0 + ((r >= 2) ? 8 : 0);
                    if (col > row) v = -1e30f;
                }
                sacc[nt][r] = v;
            }

        float rm0 = -1e30f, rm1 = -1e30f;
        #pragma unroll
        for (int nt = 0; nt < 8; ++nt) {
            rm0 = fmaxf(rm0, fmaxf(sacc[nt][0], sacc[nt][1]));
            rm1 = fmaxf(rm1, fmaxf(sacc[nt][2], sacc[nt][3]));
        }
        rm0 = fmaxf(rm0, __shfl_xor_sync(0xffffffffu, rm0, 1));
        rm0 = fmaxf(rm0, __shfl_xor_sync(0xffffffffu, rm0, 2));
        rm1 = fmaxf(rm1, __shfl_xor_sync(0xffffffffu, rm1, 1));
        rm1 = fmaxf(rm1, __shfl_xor_sync(0xffffffffu, rm1, 2));
        float nm0 = fmaxf(m0, rm0), nm1 = fmaxf(m1, rm1);
        float alpha0 = __expf(m0 - nm0), alpha1 = __expf(m1 - nm1);
        m0 = nm0; m1 = nm1;
        float rs0 = 0.f, rs1 = 0.f;
        #pragma unroll
        for (int nt = 0; nt < 8; ++nt) {
            sacc[nt][0] = __expf(sacc[nt][0] - m0); rs0 += sacc[nt][0];
            sacc[nt][1] = __expf(sacc[nt][1] - m0); rs0 += sacc[nt][1];
            sacc[nt][2] = __expf(sacc[nt][2] - m1); rs1 += sacc[nt][2];
            sacc[nt][3] = __expf(sacc[nt][3] - m1); rs1 += sacc[nt][3];
        }
        rs0 += __shfl_xor_sync(0xffffffffu, rs0, 1);
        rs0 += __shfl_xor_sync(0xffffffffu, rs0, 2);
        rs1 += __shfl_xor_sync(0xffffffffu, rs1, 1);
        rs1 += __shfl_xor_sync(0xffffffffu, rs1, 2);
        l0 = l0 * alpha0 + rs0;
        l1 = l1 * alpha1 + rs1;
        #pragma unroll
        for (int nt = 0; nt < 16; ++nt) {
            oacc[nt][0] *= alpha0; oacc[nt][1] *= alpha0;
            oacc[nt][2] *= alpha1; oacc[nt][3] *= alpha1;
        }

        // O += P V  (P split hi/lo, V hi only via ldmatrix.trans)
        #pragma unroll
        for (int kc2 = 0; kc2 < 4; ++kc2) {
            int kv0 = kc2 * 16;
            u32 ph4[4], pl4[4];
            split_pack(sacc[2*kc2][0],   sacc[2*kc2][1],   ph4[0], pl4[0]);
            split_pack(sacc[2*kc2][2],   sacc[2*kc2][3],   ph4[1], pl4[1]);
            split_pack(sacc[2*kc2+1][0], sacc[2*kc2+1][1], ph4[2], pl4[2]);
            split_pack(sacc[2*kc2+1][2], sacc[2*kc2+1][3], ph4[3], pl4[3]);
            #pragma unroll
            for (int np = 0; np < 8; ++np) {
                int d0 = np * 16 + v_col;
                u32 bh[4];
                ldsm4t(bh[0], bh[1], bh[2], bh[3], sVh + (kv0 + v_row) * FQP + d0);
                mma16816(oacc[2*np],   ph4, bh);
                mma16816(oacc[2*np],   pl4, bh);
                mma16816(oacc[2*np+1], ph4, bh + 2);
                mma16816(oacc[2*np+1], pl4, bh + 2);
            }
        }
        __syncthreads();
    }

    float inv0 = 1.f / l0, inv1 = 1.f / l1;
    int srow = qt * 64 + warp * 16 + g;
    #pragma unroll
    for (int nt = 0; nt < 16; ++nt) {
        int col = nt * 8 + 2 * tg;
        float a0 = oacc[nt][0] * inv0, a1 = oacc[nt][1] * inv0;
        float a2 = oacc[nt][2] * inv1, a3 = oacc[nt][3] * inv1;
        u32 h0, L0, h1, L1;
        split_pack(a0, a1, h0, L0);
        split_pack(a2, a3, h1, L1);
        size_t e0 = ((size_t)(b * SS + srow) * HIDDEN + h * HD + col) >> 1;
        size_t e1 = ((size_t)(b * SS + srow + 8) * HIDDEN + h * HD + col) >> 1;
        ((u32*)AtH)[e0] = h0; ((u32*)AtL)[e0] = L0;
        ((u32*)AtH)[e1] = h1; ((u32*)AtL)[e1] = L1;
    }
}

// ---------------- launch ----------------
extern "C" void kernel_launch(void* const* d_in, const int* in_sizes, int n_in,
                              void* d_out, int out_size) {
    const float* x    = (const float*)d_in[0];
    const float* Wqkv = (const float*)d_in[1];
    const float* Aqkv = (const float*)d_in[2];
    const float* Bqkv = (const float*)d_in[3];
    const float* Wo   = (const float*)d_in[4];
    const float* Ao   = (const float*)d_in[5];
    const float* Bo   = (const float*)d_in[6];
    const int*   pos  = (const int*)d_in[7];
    float* out = (float*)d_out;

    unsigned char* heap = nullptr;
    cudaGetSymbolAddress((void**)&heap, g_heap);

    size_t gemm_smem  = 2 * GSTAGE * sizeof(__half);
    size_t flash_smem = 4 * 64 * FQP * sizeof(__half);
    cudaFuncSetAttribute(gemm_split, cudaFuncAttributeMaxDynamicSharedMemorySize, (int)gemm_smem);
    cudaFuncSetAttribute(flash_attn, cudaFuncAttributeMaxDynamicSharedMemorySize, (int)flash_smem);

#define HF(off) ((__half*)(heap + off))
#define FP(off) ((float*)(heap + off))

    // 1: split x -> hi/lo
    split_fp32<<<(unsigned)((SZ_X/4 + 255) / 256), 256>>>(x, HF(O_XHI), HF(O_XLO), SZ_X/4);
    // 2-4: convert first-half weights to fp16 (hi only)
    conv_fp16<<<(unsigned)((SZ_WQKV/4 + 255) / 256), 256>>>(Wqkv, HF(O_WQH), SZ_WQKV/4);
    conv_fp16<<<(unsigned)((SZ_AQ/4 + 255) / 256), 256>>>(Aqkv, HF(O_AQH), SZ_AQ/4);
    conv_fp16<<<(unsigned)((SZ_BQ/4 + 255) / 256), 256>>>(Bqkv, HF(O_BQH), SZ_BQ/4);

    // 5: T1 = LORA_SC * x @ Aqkv^T  (hi/lo output)
    gemm_split<<<dim3(RLORA / 128, MTOT / 128), 256, gemm_smem>>>(
        HF(O_XHI), HF(O_XLO), HF(O_XHI), HF(O_XLO),
        HF(O_AQH), HF(O_AQH),
        nullptr, HF(O_T1H), HF(O_T1L),
        RLORA, HIDDEN, 0, LORA_SC);

    // 6: QKV = [x | T1] @ [Wqkv | Bqkv]^T   (fp32)   <-- ncu -s 5 captures this
    gemm_split<<<dim3(OPSZ / 128, MTOT / 128), 256, gemm_smem>>>(
        HF(O_XHI), HF(O_XLO), HF(O_T1H), HF(O_T1L),
        HF(O_WQH), HF(O_BQH),
        FP(O_QKV), nullptr, nullptr,
        OPSZ, HIDDEN, RLORA, 1.0f);

    // 7-9: convert second-half weights
    conv_fp16<<<(unsigned)((SZ_WO/4 + 255) / 256), 256>>>(Wo, HF(O_WOH), SZ_WO/4);
    conv_fp16<<<(unsigned)((SZ_AQ/4 + 255) / 256), 256>>>(Ao, HF(O_AOH), SZ_AQ/4);
    conv_fp16<<<(unsigned)((SZ_BO/4 + 255) / 256), 256>>>(Bo, HF(O_BOH), SZ_BO/4);

    // 10: RoPE + scatter + split
    rope_split<<<MTOT, 256>>>(FP(O_QKV), pos,
        HF(O_QH), HF(O_QL), HF(O_KH), HF(O_VH));

    // 11: flash attention (writes hi/lo attn directly)
    flash_attn<<<dim3(SS / 64, NHEADS, BB), 128, flash_smem>>>(
        HF(O_QH), HF(O_QL), HF(O_KH), HF(O_VH),
        HF(O_ATH), HF(O_ATL));

    // 12: T2 = LORA_SC * attn @ Ao^T  (hi/lo output)
    gemm_split<<<dim3(RLORA / 128, MTOT / 128), 256, gemm_smem>>>(
        HF(O_ATH), HF(O_ATL), HF(O_ATH), HF(O_ATL),
        HF(O_AOH), HF(O_AOH),
        nullptr, HF(O_T2H), HF(O_T2L),
        RLORA, HIDDEN, 0, LORA_SC);

    // 13: out = [attn | T2] @ [Wo | Bo]^T   (fp32)
    gemm_split<<<dim3(HIDDEN / 128, MTOT / 128), 256, gemm_smem>>>(
        HF(O_ATH), HF(O_ATL), HF(O_T2H), HF(O_T2L),
        HF(O_WOH), HF(O_BOH),
        out, nullptr, nullptr,
        HIDDEN, HIDDEN, RLORA, 1.0f);

#undef HF
#undef FP
}

// round 9
// speedup vs baseline: 2.1326x; 1.0844x over previous
#include <cuda_runtime.h>
#include <cuda_fp16.h>
#include <cstdint>
#include <cmath>

#define HIDDEN 3072
#define NHEADS 24
#define NKV 8
#define HD 128
#define ROTD 96
#define OPSZ 5120
#define RLORA 256
#define BB 2
#define SS 2048
#define MTOT (BB*SS)
#define ATT_SCALE 0.08838834764831845f
#define LORA_SC 2.0f

typedef unsigned int u32;

// ---------------- static scratch heap ----------------
constexpr size_t SZ_X    = (size_t)MTOT*HIDDEN;
constexpr size_t SZ_WQKV = (size_t)OPSZ*HIDDEN;
constexpr size_t SZ_AQ   = (size_t)RLORA*HIDDEN;
constexpr size_t SZ_BQ   = (size_t)OPSZ*RLORA;
constexpr size_t SZ_WO   = (size_t)HIDDEN*HIDDEN;
constexpr size_t SZ_BO   = (size_t)HIDDEN*RLORA;
constexpr size_t SZ_QKV  = (size_t)MTOT*OPSZ;
constexpr size_t SZ_T    = (size_t)MTOT*RLORA;
constexpr size_t SZ_Q    = (size_t)BB*NHEADS*SS*HD;
constexpr size_t SZ_KV   = (size_t)BB*NKV*SS*HD;

constexpr size_t al256(size_t x){ return (x+255)&~(size_t)255; }

constexpr size_t O_XHI = 0;
constexpr size_t O_XLO = O_XHI + al256(SZ_X*2);
constexpr size_t O_WQH = O_XLO + al256(SZ_X*2);
constexpr size_t O_AQH = O_WQH + al256(SZ_WQKV*2);
constexpr size_t O_BQH = O_AQH + al256(SZ_AQ*2);
constexpr size_t O_WOH = O_BQH + al256(SZ_BQ*2);
constexpr size_t O_AOH = O_WOH + al256(SZ_WO*2);
constexpr size_t O_BOH = O_AOH + al256(SZ_AQ*2);
constexpr size_t O_T1H = O_BOH + al256(SZ_BO*2);
constexpr size_t O_T1L = O_T1H + al256(SZ_T*2);
constexpr size_t O_T2H = O_T1L + al256(SZ_T*2);
constexpr size_t O_T2L = O_T2H + al256(SZ_T*2);
constexpr size_t O_QH  = O_T2L + al256(SZ_T*2);
constexpr size_t O_QL  = O_QH  + al256(SZ_Q*2);
constexpr size_t O_KH  = O_QL  + al256(SZ_Q*2);
constexpr size_t O_VH  = O_KH  + al256(SZ_KV*2);
constexpr size_t O_ATH = O_VH  + al256(SZ_KV*2);
constexpr size_t O_ATL = O_ATH + al256(SZ_X*2);
constexpr size_t O_QKV = O_ATL + al256(SZ_X*2);
constexpr size_t HEAP_BYTES = O_QKV + al256(SZ_QKV*4);

__device__ __align__(256) unsigned char g_heap[HEAP_BYTES];

// ---------------- helpers ----------------
__device__ __forceinline__ void mma16816(float* c, const u32* a, const u32* b) {
    asm volatile("mma.sync.aligned.m16n8k16.row.col.f32.f16.f16.f32 "
        "{%0,%1,%2,%3}, {%4,%5,%6,%7}, {%8,%9}, {%0,%1,%2,%3};\n"
        : "+f"(c[0]), "+f"(c[1]), "+f"(c[2]), "+f"(c[3])
        : "r"(a[0]), "r"(a[1]), "r"(a[2]), "r"(a[3]), "r"(b[0]), "r"(b[1]));
}
__device__ __forceinline__ void cp_async16(void* smem, const void* g) {
    u32 sa = (u32)__cvta_generic_to_shared(smem);
    asm volatile("cp.async.cg.shared.global [%0], [%1], 16;\n" :: "r"(sa), "l"(g));
}
#define CP_COMMIT() asm volatile("cp.async.commit_group;\n")
#define CP_WAIT1()  asm volatile("cp.async.wait_group 1;\n")
#define CP_WAIT0()  asm volatile("cp.async.wait_group 0;\n")

__device__ __forceinline__ void ldsm4(u32& r0, u32& r1, u32& r2, u32& r3, const __half* p) {
    u32 a = (u32)__cvta_generic_to_shared(p);
    asm volatile("ldmatrix.sync.aligned.m8n8.x4.shared.b16 {%0,%1,%2,%3}, [%4];\n"
        : "=r"(r0), "=r"(r1), "=r"(r2), "=r"(r3) : "r"(a));
}
__device__ __forceinline__ void ldsm4t(u32& r0, u32& r1, u32& r2, u32& r3, const __half* p) {
    u32 a = (u32)__cvta_generic_to_shared(p);
    asm volatile("ldmatrix.sync.aligned.m8n8.x4.trans.shared.b16 {%0,%1,%2,%3}, [%4];\n"
        : "=r"(r0), "=r"(r1), "=r"(r2), "=r"(r3) : "r"(a));
}

__device__ __forceinline__ void split_pack(float x, float y, u32& hi, u32& lo) {
    __half hx = __float2half_rn(x);
    __half hy = __float2half_rn(y);
    __half lx = __float2half_rn(x - __half2float(hx));
    __half ly = __float2half_rn(y - __half2float(hy));
    hi = ((u32)__half_as_ushort(hy) << 16) | (u32)__half_as_ushort(hx);
    lo = ((u32)__half_as_ushort(ly) << 16) | (u32)__half_as_ushort(lx);
}
__device__ __forceinline__ u32 pack_h2(float x, float y) {
    __half hx = __float2half_rn(x);
    __half hy = __float2half_rn(y);
    return ((u32)__half_as_ushort(hy) << 16) | (u32)__half_as_ushort(hx);
}

// ---------------- merged prep: split x + convert Wqkv/Aqkv/Bqkv ----------------
constexpr size_t N4_X  = SZ_X/4;
constexpr size_t N4_WQ = SZ_WQKV/4;
constexpr size_t N4_AQ = SZ_AQ/4;
constexpr size_t N4_BQ = SZ_BQ/4;
constexpr size_t N4_MAIN = N4_X + N4_WQ + N4_AQ + N4_BQ;

__global__ void prep_main(const float* __restrict__ x, const float* __restrict__ Wq,
                          const float* __restrict__ Aq, const float* __restrict__ Bq,
                          __half* __restrict__ xh, __half* __restrict__ xl,
                          __half* __restrict__ wq, __half* __restrict__ aq,
                          __half* __restrict__ bq) {
    size_t i = (size_t)blockIdx.x * blockDim.x + threadIdx.x;
    if (i >= N4_MAIN) return;
    if (i < N4_X) {
        float4 v = ((const float4*)x)[i];
        u32 h0, l0, h1, l1;
        split_pack(v.x, v.y, h0, l0);
        split_pack(v.z, v.w, h1, l1);
        ((uint2*)xh)[i] = make_uint2(h0, h1);
        ((uint2*)xl)[i] = make_uint2(l0, l1);
        return;
    }
    const float* src; __half* dst; size_t j;
    if (i < N4_X + N4_WQ)       { j = i - N4_X;                src = Wq; dst = wq; }
    else if (i < N4_X + N4_WQ + N4_AQ) { j = i - N4_X - N4_WQ; src = Aq; dst = aq; }
    else                        { j = i - N4_X - N4_WQ - N4_AQ; src = Bq; dst = bq; }
    float4 v = ((const float4*)src)[j];
    ((uint2*)dst)[j] = make_uint2(pack_h2(v.x, v.y), pack_h2(v.z, v.w));
}

constexpr size_t N4_WO = SZ_WO/4;
constexpr size_t N4_AO = SZ_AQ/4;
constexpr size_t N4_BO = SZ_BO/4;
constexpr size_t N4_SEC = N4_WO + N4_AO + N4_BO;

__global__ void prep_sec(const float* __restrict__ Wo, const float* __restrict__ Ao,
                         const float* __restrict__ Bo,
                         __half* __restrict__ wo, __half* __restrict__ ao,
                         __half* __restrict__ bo) {
    size_t i = (size_t)blockIdx.x * blockDim.x + threadIdx.x;
    if (i >= N4_SEC) return;
    const float* src; __half* dst; size_t j;
    if (i < N4_WO)              { j = i;                src = Wo; dst = wo; }
    else if (i < N4_WO + N4_AO) { j = i - N4_WO;        src = Ao; dst = ao; }
    else                        { j = i - N4_WO - N4_AO; src = Bo; dst = bo; }
    float4 v = ((const float4*)src)[j];
    ((uint2*)dst)[j] = make_uint2(pack_h2(v.x, v.y), pack_h2(v.z, v.w));
}

// ---------------- GEMM: C[M,N] = alpha * [A1|A2][M,K1+K2] @ ([B1|B2][N,K1+K2])^T ----------------
// A split hi/lo fp16 (2-pass), B fp16 hi only. GBK=64 (fewer sync iterations).
#define GBK 64
#define GPK 72
#define GARR (128*GPK)
#define GSTAGE (3*GARR)

__global__ void __launch_bounds__(256, 2) gemm_split(
    const __half* __restrict__ A1h, const __half* __restrict__ A1l,
    const __half* __restrict__ A2h, const __half* __restrict__ A2l,
    const __half* __restrict__ B1h, const __half* __restrict__ B2h,
    float* __restrict__ C,
    __half* __restrict__ Oh, __half* __restrict__ Ol,
    int N, int K1, int K2, float alpha)
{
    extern __shared__ __half sm[];
    int tid = threadIdx.x;
    int bm = blockIdx.y * 128, bn = blockIdx.x * 128;
    int warp = tid >> 5, lane = tid & 31;
    int wm = warp >> 1, wn = warp & 1;
    int g = lane >> 2, tg = lane & 3;

    auto load_stage = [&](int c) {
        int stage = c & 1;
        __half* base = sm + stage * GSTAGE;
        int k0 = c * GBK;
        bool s2 = (k0 >= K1);
        int koff = s2 ? (k0 - K1) : k0;
        int sk = s2 ? K2 : K1;
        const __half* ah = (s2 ? A2h : A1h) + koff;
        const __half* al = (s2 ? A2l : A1l) + koff;
        const __half* bh = (s2 ? B2h : B1h) + koff;
        #pragma unroll
        for (int i = 0; i < 12; ++i) {
            int t = tid + i * 256;
            int arr = t >> 10;
            int rem = t & 1023;
            int row = rem >> 3;
            int ch  = rem & 7;
            const __half* gsrc;
            if (arr == 0)      gsrc = ah + (size_t)(bm + row) * sk + ch * 8;
            else if (arr == 1) gsrc = al + (size_t)(bm + row) * sk + ch * 8;
            else               gsrc = bh + (size_t)(bn + row) * sk + ch * 8;
            cp_async16(base + arr * GARR + row * GPK + ch * 8, gsrc);
        }
        CP_COMMIT();
    };

    float acc[2][8][4];
    #pragma unroll
    for (int a = 0; a < 2; ++a)
        #pragma unroll
        for (int b = 0; b < 8; ++b)
            #pragma unroll
            for (int c = 0; c < 4; ++c) acc[a][b][c] = 0.f;

    int a_row = lane & 15;
    int a_col = (lane >> 4) << 3;
    int b_row = (lane & 7) + ((lane >> 4) << 3);
    int b_col = ((lane >> 3) & 1) << 3;

    int nkt = (K1 + K2) / GBK;
    load_stage(0);
    for (int kt = 0; kt < nkt; ++kt) {
        if (kt + 1 < nkt) load_stage(kt + 1); else CP_COMMIT();
        CP_WAIT1();
        __syncthreads();
        const __half* base = sm + (kt & 1) * GSTAGE;
        const __half* sAh = base;
        const __half* sAl = base + GARR;
        const __half* sBh = base + 2 * GARR;
        #pragma unroll
        for (int ks = 0; ks < 4; ++ks) {
            int k0 = ks * 16;
            u32 ah[2][4], al[2][4];
            #pragma unroll
            for (int mt = 0; mt < 2; ++mt) {
                int r0 = wm * 32 + mt * 16 + a_row;
                ldsm4(ah[mt][0], ah[mt][1], ah[mt][2], ah[mt][3], sAh + r0 * GPK + k0 + a_col);
                ldsm4(al[mt][0], al[mt][1], al[mt][2], al[mt][3], sAl + r0 * GPK + k0 + a_col);
            }
            #pragma unroll
            for (int np = 0; np < 4; ++np) {
                int n0 = wn * 64 + np * 16 + b_row;
                u32 bh[4];
                ldsm4(bh[0], bh[1], bh[2], bh[3], sBh + n0 * GPK + k0 + b_col);
                #pragma unroll
                for (int mt = 0; mt < 2; ++mt) {
                    mma16816(acc[mt][2*np],   ah[mt], bh);
                    mma16816(acc[mt][2*np],   al[mt], bh);
                    mma16816(acc[mt][2*np+1], ah[mt], bh + 2);
                    mma16816(acc[mt][2*np+1], al[mt], bh + 2);
                }
            }
        }
        __syncthreads();
    }

    #pragma unroll
    for (int mt = 0; mt < 2; ++mt)
        #pragma unroll
        for (int nt = 0; nt < 8; ++nt) {
            int row = bm + wm * 32 + mt * 16 + g;
            int col = bn + wn * 64 + nt * 8 + 2 * tg;
            float v0 = alpha * acc[mt][nt][0], v1 = alpha * acc[mt][nt][1];
            float v2 = alpha * acc[mt][nt][2], v3 = alpha * acc[mt][nt][3];
            if (Oh) {
                u32 h0, l0, h1, l1;
                split_pack(v0, v1, h0, l0);
                split_pack(v2, v3, h1, l1);
                size_t i0 = ((size_t)row * N + col) >> 1;
                size_t i1 = ((size_t)(row + 8) * N + col) >> 1;
                ((u32*)Oh)[i0] = h0; ((u32*)Ol)[i0] = l0;
                ((u32*)Oh)[i1] = h1; ((u32*)Ol)[i1] = l1;
            } else {
                float* p0 = C + (size_t)row * N + col;
                float* p1 = C + (size_t)(row + 8) * N + col;
                p0[0] = v0; p0[1] = v1;
                p1[0] = v2; p1[1] = v3;
            }
        }
}

// ---------------- RoPE + split + scatter to [b,h,s,d] ----------------
__global__ void __launch_bounds__(256) rope_split(
    const float* __restrict__ qkv, const int* __restrict__ pos_ids,
    __half* __restrict__ Qh, __half* __restrict__ Ql,
    __half* __restrict__ Kh, __half* __restrict__ Vh)
{
    int bs = blockIdx.x;
    int b = bs / SS, s = bs % SS;
    __shared__ float cosv[ROTD], sinv[ROTD];
    int tid = threadIdx.x;
    if (tid < 48) {
        float invf = (float)pow(10000.0, -(double)tid / 48.0);
        float ang = (float)pos_ids[bs] * invf;
        float c = (float)cos((double)ang), sn = (float)sin((double)ang);
        cosv[tid] = c; cosv[tid + 48] = c;
        sinv[tid] = sn; sinv[tid + 48] = sn;
    }
    __syncthreads();
    const float* src = qkv + (size_t)bs * OPSZ;
    for (int e = tid; e < OPSZ; e += 256) {
        int d = e & 127;
        int hh = e >> 7;
        float v = src[e];
        bool isq = hh < NHEADS;
        bool isk = (hh >= NHEADS) && (hh < NHEADS + NKV);
        float outv = v;
        if ((isq || isk) && d < ROTD) {
            if (d < 48) outv = v * cosv[d] - src[e + 48] * sinv[d];
            else        outv = v * cosv[d] + src[e - 48] * sinv[d];
        }
        if (isq) {
            __half hi = __float2half_rn(outv);
            __half lo = __float2half_rn(outv - __half2float(hi));
            size_t dst = ((size_t)(b * NHEADS + hh) * SS + s) * HD + d;
            Qh[dst] = hi; Ql[dst] = lo;
        } else if (isk) {
            size_t dst = ((size_t)(b * NKV + (hh - NHEADS)) * SS + s) * HD + d;
            Kh[dst] = __float2half_rn(outv);
        } else {
            size_t dst = ((size_t)(b * NKV + (hh - NHEADS - NKV)) * SS + s) * HD + d;
            Vh[dst] = __float2half_rn(outv);
        }
    }
}

// ---------------- causal flash attention (GQA), fp16 2-pass, ldmatrix ----------------
#define FQP 136

__global__ void __launch_bounds__(128) flash_attn(
    const __half* __restrict__ Qh, const __half* __restrict__ Ql,
    const __half* __restrict__ Kh, const __half* __restrict__ Vh,
    __half* __restrict__ AtH, __half* __restrict__ AtL)
{
    extern __shared__ __half fsm[];
    __half* sQh = fsm;
    __half* sQl = fsm + 1 * 64 * FQP;
    __half* sKh = fsm + 2 * 64 * FQP;
    __half* sVh = fsm + 3 * 64 * FQP;

    int qt = blockIdx.x, h = blockIdx.y, b = blockIdx.z;
    int kvh = h / (NHEADS / NKV);
    int tid = threadIdx.x, warp = tid >> 5, lane = tid & 31;
    int g = lane >> 2, tg = lane & 3;

    int a_row = warp * 16 + (lane & 15);
    int a_col = (lane >> 4) << 3;
    int b_row = (lane & 7) + ((lane >> 4) << 3);
    int b_col = ((lane >> 3) & 1) << 3;
    int v_row = (lane & 7) + (((lane >> 3) & 1) << 3);
    int v_col = ((lane >> 4) & 1) << 3;

    size_t qbase = ((size_t)(b * NHEADS + h) * SS + (size_t)qt * 64) * HD;
    #pragma unroll
    for (int i = 0; i < 8; ++i) {
        int task = tid + i * 128;
        int row = task >> 4, ch = task & 15;
        cp_async16(sQh + row * FQP + ch * 8, Qh + qbase + row * HD + ch * 8);
        cp_async16(sQl + row * FQP + ch * 8, Ql + qbase + row * HD + ch * 8);
    }
    CP_COMMIT();

    float m0 = -1e30f, m1 = -1e30f, l0 = 0.f, l1 = 0.f;
    float oacc[16][4];
    #pragma unroll
    for (int i = 0; i < 16; ++i)
        #pragma unroll
        for (int r = 0; r < 4; ++r) oacc[i][r] = 0.f;

    for (int kt = 0; kt <= qt; ++kt) {
        size_t kbase = ((size_t)(b * NKV + kvh) * SS + (size_t)kt * 64) * HD;
        #pragma unroll
        for (int i = 0; i < 8; ++i) {
            int task = tid + i * 128;
            int row = task >> 4, ch = task & 15;
            cp_async16(sKh + row * FQP + ch * 8, Kh + kbase + row * HD + ch * 8);
            cp_async16(sVh + row * FQP + ch * 8, Vh + kbase + row * HD + ch * 8);
        }
        CP_COMMIT();
        CP_WAIT0();
        __syncthreads();

        float sacc[8][4];
        #pragma unroll
        for (int nt = 0; nt < 8; ++nt)
            #pragma unroll
            for (int r = 0; r < 4; ++r) sacc[nt][r] = 0.f;

        #pragma unroll
        for (int kc = 0; kc < 8; ++kc) {
            int k0 = kc * 16;
            u32 ah[4], al[4];
            ldsm4(ah[0], ah[1], ah[2], ah[3], sQh + a_row * FQP + k0 + a_col);
            ldsm4(al[0], al[1], al[2], al[3], sQl + a_row * FQP + k0 + a_col);
            #pragma unroll
            for (int np = 0; np < 4; ++np) {
                int n0 = np * 16 + b_row;
                u32 bh[4];
                ldsm4(bh[0], bh[1], bh[2], bh[3], sKh + n0 * FQP + k0 + b_col);
                mma16816(sacc[2*np],   ah, bh);
                mma16816(sacc[2*np],   al, bh);
                mma16816(sacc[2*np+1], ah, bh + 2);
                mma16816(sacc[2*np+1], al, bh + 2);
            }
        }

        bool diag = (kt == qt);
        int row0 = qt * 64 + warp * 16 + g;
        #pragma unroll
        for (int nt = 0; nt < 8; ++nt)
            #pragma unroll
            for (int r = 0; r < 4; ++r) {
                float v = sacc[nt][r] * ATT_SCALE;
                if (diag) {
                    int col = kt * 64 + nt * 8 + 2 * tg + (r & 1);
                    int row = row0 + ((r >= 2) ? 8 : 0);
                    if (col > row) v = -1e30f;
                }
                sacc[nt][r] = v;
            }

        float rm0 = -1e30f, rm1 = -1e30f;
        #pragma unroll
        for (int nt = 0; nt < 8; ++nt) {
            rm0 = fmaxf(rm0, fmaxf(sacc[nt][0], sacc[nt][1]));
            rm1 = fmaxf(rm1, fmaxf(sacc[nt][2], sacc[nt][3]));
        }
        rm0 = fmaxf(rm0, __shfl_xor_sync(0xffffffffu, rm0, 1));
        rm0 = fmaxf(rm0, __shfl_xor_sync(0xffffffffu, rm0, 2));
        rm1 = fmaxf(rm1, __shfl_xor_sync(0xffffffffu, rm1, 1));
        rm1 = fmaxf(rm1, __shfl_xor_sync(0xffffffffu, rm1, 2));
        float nm0 = fmaxf(m0, rm0), nm1 = fmaxf(m1, rm1);
        float alpha0 = __expf(m0 - nm0), alpha1 = __expf(m1 - nm1);
        m0 = nm0; m1 = nm1;
        float rs0 = 0.f, rs1 = 0.f;
        #pragma unroll
        for (int nt = 0; nt < 8; ++nt) {
            sacc[nt][0] = __expf(sacc[nt][0] - m0); rs0 += sacc[nt][0];
            sacc[nt][1] = __expf(sacc[nt][1] - m0); rs0 += sacc[nt][1];
            sacc[nt][2] = __expf(sacc[nt][2] - m1); rs1 += sacc[nt][2];
            sacc[nt][3] = __expf(sacc[nt][3] - m1); rs1 += sacc[nt][3];
        }
        rs0 += __shfl_xor_sync(0xffffffffu, rs0, 1);
        rs0 += __shfl_xor_sync(0xffffffffu, rs0, 2);
        rs1 += __shfl_xor_sync(0xffffffffu, rs1, 1);
        rs1 += __shfl_xor_sync(0xffffffffu, rs1, 2);
        l0 = l0 * alpha0 + rs0;
        l1 = l1 * alpha1 + rs1;
        #pragma unroll
        for (int nt = 0; nt < 16; ++nt) {
            oacc[nt][0] *= alpha0; oacc[nt][1] *= alpha0;
            oacc[nt][2] *= alpha1; oacc[nt][3] *= alpha1;
        }

        #pragma unroll
        for (int kc2 = 0; kc2 < 4; ++kc2) {
            int kv0 = kc2 * 16;
            u32 ph4[4], pl4[4];
            split_pack(sacc[2*kc2][0],   sacc[2*kc2][1],   ph4[0], pl4[0]);
            split_pack(sacc[2*kc2][2],   sacc[2*kc2][3],   ph4[1], pl4[1]);
            split_pack(sacc[2*kc2+1][0], sacc[2*kc2+1][1], ph4[2], pl4[2]);
            split_pack(sacc[2*kc2+1][2], sacc[2*kc2+1][3], ph4[3], pl4[3]);
            #pragma unroll
            for (int np = 0; np < 8; ++np) {
                int d0 = np * 16 + v_col;
                u32 bh[4];
                ldsm4t(bh[0], bh[1], bh[2], bh[3], sVh + (kv0 + v_row) * FQP + d0);
                mma16816(oacc[2*np],   ph4, bh);
                mma16816(oacc[2*np],   pl4, bh);
                mma16816(oacc[2*np+1], ph4, bh + 2);
                mma16816(oacc[2*np+1], pl4, bh + 2);
            }
        }
        __syncthreads();
    }

    float inv0 = 1.f / l0, inv1 = 1.f / l1;
    int srow = qt * 64 + warp * 16 + g;
    #pragma unroll
    for (int nt = 0; nt < 16; ++nt) {
        int col = nt * 8 + 2 * tg;
        float a0 = oacc[nt][0] * inv0, a1 = oacc[nt][1] * inv0;
        float a2 = oacc[nt][2] * inv1, a3 = oacc[nt][3] * inv1;
        u32 h0, L0, h1, L1;
        split_pack(a0, a1, h0, L0);
        split_pack(a2, a3, h1, L1);
        size_t e0 = ((size_t)(b * SS + srow) * HIDDEN + h * HD + col) >> 1;
        size_t e1 = ((size_t)(b * SS + srow + 8) * HIDDEN + h * HD + col) >> 1;
        ((u32*)AtH)[e0] = h0; ((u32*)AtL)[e0] = L0;
        ((u32*)AtH)[e1] = h1; ((u32*)AtL)[e1] = L1;
    }
}

// ---------------- launch ----------------
extern "C" void kernel_launch(void* const* d_in, const int* in_sizes, int n_in,
                              void* d_out, int out_size) {
    const float* x    = (const float*)d_in[0];
    const float* Wqkv = (const float*)d_in[1];
    const float* Aqkv = (const float*)d_in[2];
    const float* Bqkv = (const float*)d_in[3];
    const float* Wo   = (const float*)d_in[4];
    const float* Ao   = (const float*)d_in[5];
    const float* Bo   = (const float*)d_in[6];
    const int*   pos  = (const int*)d_in[7];
    float* out = (float*)d_out;

    unsigned char* heap = nullptr;
    cudaGetSymbolAddress((void**)&heap, g_heap);

    size_t gemm_smem  = 2 * GSTAGE * sizeof(__half);
    size_t flash_smem = 4 * 64 * FQP * sizeof(__half);
    cudaFuncSetAttribute(gemm_split, cudaFuncAttributeMaxDynamicSharedMemorySize, (int)gemm_smem);
    cudaFuncSetAttribute(flash_attn, cudaFuncAttributeMaxDynamicSharedMemorySize, (int)flash_smem);

#define HF(off) ((__half*)(heap + off))
#define FP(off) ((float*)(heap + off))

    // 1: prep x + first-half weights
    prep_main<<<(unsigned)((N4_MAIN + 255) / 256), 256>>>(
        x, Wqkv, Aqkv, Bqkv,
        HF(O_XHI), HF(O_XLO), HF(O_WQH), HF(O_AQH), HF(O_BQH));

    // 2: T1 = LORA_SC * x @ Aqkv^T  (hi/lo output)
    gemm_split<<<dim3(RLORA / 128, MTOT / 128), 256, gemm_smem>>>(
        HF(O_XHI), HF(O_XLO), HF(O_XHI), HF(O_XLO),
        HF(O_AQH), HF(O_AQH),
        nullptr, HF(O_T1H), HF(O_T1L),
        RLORA, HIDDEN, 0, LORA_SC);

    // 3: prep second-half weights (independent filler so QKV lands in the ncu slot)
    prep_sec<<<(unsigned)((N4_SEC + 255) / 256), 256>>>(
        Wo, Ao, Bo, HF(O_WOH), HF(O_AOH), HF(O_BOH));

    // 4: QKV = [x | T1] @ [Wqkv | Bqkv]^T   (fp32)   <-- ncu profiled slot
    gemm_split<<<dim3(OPSZ / 128, MTOT / 128), 256, gemm_smem>>>(
        HF(O_XHI), HF(O_XLO), HF(O_T1H), HF(O_T1L),
        HF(O_WQH), HF(O_BQH),
        FP(O_QKV), nullptr, nullptr,
        OPSZ, HIDDEN, RLORA, 1.0f);

    // 5: RoPE + scatter + split
    rope_split<<<MTOT, 256>>>(FP(O_QKV), pos,
        HF(O_QH), HF(O_QL), HF(O_KH), HF(O_VH));

    // 6: flash attention (writes hi/lo attn directly)
    flash_attn<<<dim3(SS / 64, NHEADS, BB), 128, flash_smem>>>(
        HF(O_QH), HF(O_QL), HF(O_KH), HF(O_VH),
        HF(O_ATH), HF(O_ATL));

    // 7: T2 = LORA_SC * attn @ Ao^T  (hi/lo output)
    gemm_split<<<dim3(RLORA / 128, MTOT / 128), 256, gemm_smem>>>(
        HF(O_ATH), HF(O_ATL), HF(O_ATH), HF(O_ATL),
        HF(O_AOH), HF(O_AOH),
        nullptr, HF(O_T2H), HF(O_T2L),
        RLORA, HIDDEN, 0, LORA_SC);

    // 8: out = [attn | T2] @ [Wo | Bo]^T   (fp32)
    gemm_split<<<dim3(HIDDEN / 128, MTOT / 128), 256, gemm_smem>>>(
        HF(O_ATH), HF(O_ATL), HF(O_T2H), HF(O_T2L),
        HF(O_WOH), HF(O_BOH),
        out, nullptr, nullptr,
        HIDDEN, HIDDEN, RLORA, 1.0f);

#undef HF
#undef FP
}